// round 11
// baseline (speedup 1.0000x reference)
#include <cuda_runtime.h>
#include <cuda_fp16.h>
#include <math.h>
#include <stdint.h>

#define BATCH 2
#define SEQ   4096
#define DIM   128
#define NTOK  (BATCH * SEQ)
#define SCALE 0.125f   // 64^-0.5
#define NSPLIT 2
#define JT_PER_SPLIT (64 / NSPLIT)

// ---------------- device scratch ----------------
__device__ float  g_W[640 * 128];
__device__ float  g_q[NTOK * DIM];            // reused as h1 after flash
__device__ __half g_kh[NTOK * DIM];
__device__ __half g_kl[NTOK * DIM];
__device__ __half g_vh[(size_t)DIM * NTOK];   // V fp16, transposed [d][tok]
__device__ float  g_sq[NTOK];
__device__ __half g_dist[(size_t)BATCH * SEQ * SEQ];
__device__ double g_sum_spe;
__device__ float  g_inv2s2_spe;
__device__ float  g_spa[64 * 64];
__device__ float  g_attn[NTOK * DIM];
__device__ float  g_po[NSPLIT][NTOK * DIM];
__device__ float2 g_pml[NSPLIT][NTOK * 2];
__device__ unsigned int g_dist_ctr = 0;

// ---------------- helpers ----------------
__device__ __forceinline__ uint32_t f2tf(float f) {
    uint32_t r; asm("cvt.rna.tf32.f32 %0, %1;" : "=r"(r) : "f"(f)); return r;
}
__device__ __forceinline__ void mma8(float* c, const uint32_t* a, uint32_t b0, uint32_t b1) {
    asm volatile("mma.sync.aligned.m16n8k8.row.col.f32.tf32.tf32.f32 "
                 "{%0,%1,%2,%3},{%4,%5,%6,%7},{%8,%9},{%0,%1,%2,%3};"
                 : "+f"(c[0]), "+f"(c[1]), "+f"(c[2]), "+f"(c[3])
                 : "r"(a[0]), "r"(a[1]), "r"(a[2]), "r"(a[3]), "r"(b0), "r"(b1));
}
__device__ __forceinline__ void mma16(float* c, const uint32_t* a, uint32_t b0, uint32_t b1) {
    asm volatile("mma.sync.aligned.m16n8k16.row.col.f32.f16.f16.f32 "
                 "{%0,%1,%2,%3},{%4,%5,%6,%7},{%8,%9},{%0,%1,%2,%3};"
                 : "+f"(c[0]), "+f"(c[1]), "+f"(c[2]), "+f"(c[3])
                 : "r"(a[0]), "r"(a[1]), "r"(a[2]), "r"(a[3]), "r"(b0), "r"(b1));
}

// ---------------- weight norm ----------------
__global__ void k_weights(const float* __restrict__ vq, const float* __restrict__ gq,
                          const float* __restrict__ v1, const float* __restrict__ g1,
                          const float* __restrict__ v2, const float* __restrict__ g2) {
    int r = blockIdx.x, t = threadIdx.x;
    if (r == 0 && t == 0) g_sum_spe = 0.0;
    const float* v; float g;
    if (r < 384)      { v = vq + r * 128;        g = gq[r]; }
    else if (r < 512) { v = v1 + (r - 384) * 128; g = g1[r - 384]; }
    else              { v = v2 + (r - 512) * 128; g = g2[r - 512]; }
    float val = v[t];
    float ss = val * val;
    #pragma unroll
    for (int o = 16; o; o >>= 1) ss += __shfl_xor_sync(0xffffffffu, ss, o);
    __shared__ float ws[4];
    if ((t & 31) == 0) ws[t >> 5] = ss;
    __syncthreads();
    float tot = ws[0] + ws[1] + ws[2] + ws[3];
    g_W[r * 128 + t] = val * (g / sqrtf(tot));
}

// ---------------- per-token ||x||^2 ----------------
__global__ void k_sq(const float* __restrict__ x) {
    int token = blockIdx.x * 8 + (threadIdx.x >> 5);
    int lane  = threadIdx.x & 31;
    const float4* xp = (const float4*)(x + (size_t)token * 128);
    float4 a = xp[lane];
    float ss = a.x * a.x + a.y * a.y + a.z * a.z + a.w * a.w;
    #pragma unroll
    for (int o = 16; o; o >>= 1) ss += __shfl_xor_sync(0xffffffffu, ss, o);
    if (lane == 0) g_sq[token] = ss;
}

// ---------------- tiled projection GEMM (scalar fp32, exact) ----------------
__global__ void __launch_bounds__(256) k_gemm64(const float* __restrict__ A,
                                                const float* __restrict__ Wrows,
                                                const float* __restrict__ bias,
                                                float* __restrict__ out, int mode) {
    extern __shared__ float sm[];
    float* aT = sm;
    float* wT = sm + 128 * 68;
    int c0 = blockIdx.x * 64;
    int t0 = blockIdx.y * 64;
    int tid = threadIdx.x;
    for (int idx = tid; idx < 64 * 128; idx += 256) {
        int r = idx >> 7, k = idx & 127;
        aT[k * 68 + r] = A[(t0 + r) * 128 + k];
        wT[k * 68 + r] = Wrows[(c0 + r) * 128 + k];
    }
    __syncthreads();
    int ty = tid >> 4, tx = tid & 15;
    float acc[4][4] = {};
    #pragma unroll 4
    for (int k = 0; k < 128; k++) {
        float4 av = *(const float4*)&aT[k * 68 + 4 * ty];
        float4 bv = *(const float4*)&wT[k * 68 + 4 * tx];
        float a[4] = {av.x, av.y, av.z, av.w};
        float c[4] = {bv.x, bv.y, bv.z, bv.w};
        #pragma unroll
        for (int i = 0; i < 4; i++)
            #pragma unroll
            for (int j = 0; j < 4; j++) acc[i][j] = fmaf(a[i], c[j], acc[i][j]);
    }
    #pragma unroll
    for (int i = 0; i < 4; i++) {
        int token = t0 + 4 * ty + i;
        #pragma unroll
        for (int j = 0; j < 4; j++) {
            int c = c0 + 4 * tx + j;
            float val = acc[i][j] + __ldg(&bias[c]);
            if (mode == 0) {
                if (c < 128) {
                    g_q[token * 128 + c] = val;
                } else if (c < 256) {
                    int d = c - 128;
                    __half hi = __float2half_rn(val);
                    __half lo = __float2half_rn(val - __half2float(hi));
                    g_kh[token * 128 + d] = hi;
                    g_kl[token * 128 + d] = lo;
                } else {
                    int d = c - 256;
                    g_vh[(size_t)d * NTOK + token] = __float2half_rn(val);
                }
            } else if (mode == 1) {
                g_q[token * 128 + c] = 0.5f * val * (1.0f + erff(val * 0.70710678118654752f));
            } else {
                out[token * 128 + c] = val;
            }
        }
    }
}

// ---------------- pairwise distance via tf32 MMA, finalize fused (last CTA) ----------------
__global__ void __launch_bounds__(256) k_dist(const float* __restrict__ x) {
    extern __shared__ float sm[];
    float* xi = sm;              // [128][132], tf32-rounded
    float* xj = sm + 128 * 132;
    int b = blockIdx.z, i0 = blockIdx.y * 128, j0 = blockIdx.x * 128;
    int tid = threadIdx.x;
    for (int fi = tid; fi < 4096; fi += 256) {
        int r = fi >> 5, c4 = (fi & 31) * 4;
        float4 a = *(const float4*)&x[(size_t)(b * SEQ + i0 + r) * 128 + c4];
        float4 bb = *(const float4*)&x[(size_t)(b * SEQ + j0 + r) * 128 + c4];
        a.x = __uint_as_float(f2tf(a.x)); a.y = __uint_as_float(f2tf(a.y));
        a.z = __uint_as_float(f2tf(a.z)); a.w = __uint_as_float(f2tf(a.w));
        bb.x = __uint_as_float(f2tf(bb.x)); bb.y = __uint_as_float(f2tf(bb.y));
        bb.z = __uint_as_float(f2tf(bb.z)); bb.w = __uint_as_float(f2tf(bb.w));
        *(float4*)&xi[r * 132 + c4] = a;
        *(float4*)&xj[r * 132 + c4] = bb;
    }
    __syncthreads();
    int lane = tid & 31, w = tid >> 5;
    int wr = w >> 1, wc = w & 1;
    int g = lane >> 2, t = lane & 3;
    float c[2][8][4] = {};
    #pragma unroll 1
    for (int ks = 0; ks < 16; ks++) {
        uint32_t A[2][4];
        #pragma unroll
        for (int mt = 0; mt < 2; mt++)
            #pragma unroll
            for (int e = 0; e < 4; e++)
                A[mt][e] = __float_as_uint(xi[(32 * wr + 16 * mt + g + 8 * (e & 1)) * 132 + 8 * ks + t + 4 * (e >> 1)]);
        #pragma unroll
        for (int nt = 0; nt < 8; nt++) {
            int row = (64 * wc + 8 * nt + g) * 132 + 8 * ks + t;
            uint32_t b0 = __float_as_uint(xj[row]);
            uint32_t b1 = __float_as_uint(xj[row + 4]);
            mma8(c[0][nt], A[0], b0, b1);
            mma8(c[1][nt], A[1], b0, b1);
        }
    }
    float lsum = 0.f;
    #pragma unroll
    for (int mt = 0; mt < 2; mt++) {
        int ir0 = i0 + 32 * wr + 16 * mt + g;
        float sqi0 = __ldg(&g_sq[b * SEQ + ir0]);
        float sqi1 = __ldg(&g_sq[b * SEQ + ir0 + 8]);
        #pragma unroll
        for (int nt = 0; nt < 8; nt++) {
            int jc = j0 + 64 * wc + 8 * nt + 2 * t;
            float sj0 = __ldg(&g_sq[b * SEQ + jc]);
            float sj1 = __ldg(&g_sq[b * SEQ + jc + 1]);
            float d00 = sqrtf(fmaxf(sqi0 + sj0 - 2.f * c[mt][nt][0], 0.f));
            float d01 = sqrtf(fmaxf(sqi0 + sj1 - 2.f * c[mt][nt][1], 0.f));
            float d10 = sqrtf(fmaxf(sqi1 + sj0 - 2.f * c[mt][nt][2], 0.f));
            float d11 = sqrtf(fmaxf(sqi1 + sj1 - 2.f * c[mt][nt][3], 0.f));
            lsum += d00 + d01 + d10 + d11;
            *(__half2*)&g_dist[(size_t)(b * SEQ + ir0) * SEQ + jc]     = __floats2half2_rn(d00, d01);
            *(__half2*)&g_dist[(size_t)(b * SEQ + ir0 + 8) * SEQ + jc] = __floats2half2_rn(d10, d11);
        }
    }
    #pragma unroll
    for (int o = 16; o; o >>= 1) lsum += __shfl_xor_sync(0xffffffffu, lsum, o);
    __shared__ float rsum[8];
    if (lane == 0) rsum[w] = lsum;
    __syncthreads();
    __shared__ bool is_last;
    if (tid == 0) {
        float tot = 0.f;
        #pragma unroll
        for (int i = 0; i < 8; i++) tot += rsum[i];
        atomicAdd(&g_sum_spe, (double)tot);
        __threadfence();
        unsigned int n = gridDim.x * gridDim.y * gridDim.z;
        unsigned int cdone = atomicAdd(&g_dist_ctr, 1u);
        is_last = (cdone == n - 1);
    }
    __syncthreads();
    if (!is_last) return;

    int t2 = tid;
    __shared__ double red[256];
    double local = 0.0;
    for (int idx = t2; idx < 64 * 64; idx += 256) {
        int adx = idx >> 6, ady = idx & 63;
        double cx = adx ? 2.0 * (64 - adx) : 64.0;
        double cy = ady ? 2.0 * (64 - ady) : 64.0;
        local += cx * cy * sqrt((double)(adx * adx + ady * ady));
    }
    red[t2] = local; __syncthreads();
    for (int s = 128; s; s >>= 1) { if (t2 < s) red[t2] += red[t2 + s]; __syncthreads(); }
    __shared__ float inv_spa;
    if (t2 == 0) {
        double sig_spa = red[0] / ((double)SEQ * (double)SEQ);
        inv_spa = (float)(1.0 / (2.0 * sig_spa * sig_spa));
        double sig_spe = g_sum_spe / ((double)BATCH * (double)SEQ * (double)SEQ);
        g_inv2s2_spe = (float)(1.0 / (2.0 * sig_spe * sig_spe));
        g_dist_ctr = 0;
    }
    __syncthreads();
    float iv = inv_spa;
    for (int idx = t2; idx < 64 * 64; idx += 256) {
        int adx = idx >> 6, ady = idx & 63;
        g_spa[idx] = expf(-sqrtf((float)(adx * adx + ady * ady)) * iv);
    }
}

// ---------------- flash attention: M=128, fp16 MMA, Q staged in smem (spill fix) ----------------
// smem halves: KH[64][136]@0, KL@8704, V[128][136]@17408, Q[128][136]@34816, WS@52224 (128x72)
#define SMQ_OFF 34816
#define WS_HOFF 52224
#define FLASH_SMEM_BYTES ((WS_HOFF + 128 * 72) * 2)   // 122880
__global__ void __launch_bounds__(256, 1) k_flash() {
    extern __shared__ char smraw[];
    __half* smKH = (__half*)smraw;
    __half* smKL = smKH + 64 * 136;
    __half* smV  = smKH + 2 * 64 * 136;
    __half* smQ  = smKH + SMQ_OFF;
    __half* smWS = smKH + WS_HOFF;
    int b     = blockIdx.z;
    int split = blockIdx.y;
    int i0 = blockIdx.x * 128;
    int tid = threadIdx.x;
    int lane = tid & 31, w = tid >> 5;
    int h = w >> 2, mq = w & 3;
    int g = lane >> 2, t = lane & 3;
    int hb = h * 64;
    int rbase = 32 * mq;
    float inv_spe = g_inv2s2_spe;

    // ---- stage Q (fp16 hi) once ----
    for (int fi = tid; fi < 4096; fi += 256) {
        int r = fi >> 5, c4 = (fi & 31) * 4;
        float4 qv = *(const float4*)&g_q[(size_t)(b * SEQ + i0 + r) * 128 + c4];
        __half2 h01 = __floats2half2_rn(qv.x, qv.y);
        __half2 h23 = __floats2half2_rn(qv.z, qv.w);
        uint2 u = {*(uint32_t*)&h01, *(uint32_t*)&h23};
        *(uint2*)&smQ[r * 136 + c4] = u;
    }

    float co[2][8][4] = {};
    float mA[2] = {-1e30f, -1e30f}, mB[2] = {-1e30f, -1e30f};
    float lA[2] = {0.f, 0.f},       lB[2] = {0.f, 0.f};

    int jt_begin = split * JT_PER_SPLIT;
    for (int jt = jt_begin; jt < jt_begin + JT_PER_SPLIT; jt++) {
        int j0 = jt * 64;
        if (jt != jt_begin) __syncthreads();   // everyone done reading previous KV/WS
        // ---- fill K hi/lo + V planes ----
        #pragma unroll
        for (int fi = tid; fi < 3072; fi += 256) {
            if (fi < 1024) {
                int r = fi >> 4, c = fi & 15;
                *(uint4*)&smKH[r * 136 + c * 8] =
                    *(const uint4*)&g_kh[(size_t)(b * SEQ + j0 + r) * 128 + c * 8];
            } else if (fi < 2048) {
                int v = fi - 1024, r = v >> 4, c = v & 15;
                *(uint4*)&smKL[r * 136 + c * 8] =
                    *(const uint4*)&g_kl[(size_t)(b * SEQ + j0 + r) * 128 + c * 8];
            } else {
                int v = fi - 2048, d = v >> 3, c = v & 7;
                *(uint4*)&smV[d * 136 + c * 8] =
                    *(const uint4*)&g_vh[(size_t)d * NTOK + b * SEQ + j0 + c * 8];
            }
        }
        // ---- mask tile (128 rows x 64 cols, half2) ----
        int jx = j0 >> 6;
        #pragma unroll
        for (int ii = tid; ii < 4096; ii += 256) {
            int i = ii >> 5, c2 = (ii & 31) * 2;
            __half2 d2 = *(const __half2*)&g_dist[(size_t)(b * SEQ + i0 + i) * SEQ + j0 + c2];
            float2 df = __half22float2(d2);
            int gi = i0 + i;
            int adx = abs((gi >> 6) - jx);
            int gyi = gi & 63;
            const float* spaRow = &g_spa[adx * 64];
            float w0 = spaRow[abs(gyi - c2)] * __expf(-df.x * inv_spe);
            float w1 = spaRow[abs(gyi - (c2 + 1))] * __expf(-df.y * inv_spe);
            *(__half2*)&smWS[i * 72 + c2] = __floats2half2_rn(w0, w1);
        }
        __syncthreads();

        // ---- QK^T: 2-term fp16, Q frags from smem per ks, K frags hoisted across m ----
        float cs[2][8][4] = {};
        #pragma unroll
        for (int ks = 0; ks < 4; ks++) {
            uint32_t qf[2][4];
            #pragma unroll
            for (int m = 0; m < 2; m++)
                #pragma unroll
                for (int e = 0; e < 4; e++) {
                    int row = rbase + 16 * m + g + (e & 1) * 8;
                    int col = hb + 16 * ks + 2 * t + (e >> 1) * 8;
                    qf[m][e] = *(const uint32_t*)&smQ[row * 136 + col];
                }
            #pragma unroll
            for (int nt = 0; nt < 8; nt++) {
                int base = (8 * nt + g) * 136 + hb + 16 * ks + 2 * t;
                uint32_t kh0 = *(const uint32_t*)&smKH[base];
                uint32_t kh1 = *(const uint32_t*)&smKH[base + 8];
                uint32_t kl0 = *(const uint32_t*)&smKL[base];
                uint32_t kl1 = *(const uint32_t*)&smKL[base + 8];
                mma16(cs[0][nt], qf[0], kh0, kh1);
                mma16(cs[0][nt], qf[0], kl0, kl1);
                mma16(cs[1][nt], qf[1], kh0, kh1);
                mma16(cs[1][nt], qf[1], kl0, kl1);
            }
        }

        // ---- mask + online softmax per m ----
        uint32_t plo[2][8], phi[2][8];
        #pragma unroll
        for (int m = 0; m < 2; m++) {
            int r0 = rbase + 16 * m + g;
            float mloc0 = -1e30f, mloc1 = -1e30f;
            #pragma unroll
            for (int nt = 0; nt < 8; nt++) {
                int col = 8 * nt + 2 * t;
                float2 wa = __half22float2(*(const __half2*)&smWS[r0 * 72 + col]);
                float2 wb = __half22float2(*(const __half2*)&smWS[(r0 + 8) * 72 + col]);
                cs[m][nt][0] *= SCALE * wa.x; cs[m][nt][1] *= SCALE * wa.y;
                cs[m][nt][2] *= SCALE * wb.x; cs[m][nt][3] *= SCALE * wb.y;
                mloc0 = fmaxf(mloc0, fmaxf(cs[m][nt][0], cs[m][nt][1]));
                mloc1 = fmaxf(mloc1, fmaxf(cs[m][nt][2], cs[m][nt][3]));
            }
            #pragma unroll
            for (int o = 1; o <= 2; o <<= 1) {
                mloc0 = fmaxf(mloc0, __shfl_xor_sync(0xffffffffu, mloc0, o));
                mloc1 = fmaxf(mloc1, __shfl_xor_sync(0xffffffffu, mloc1, o));
            }
            float mn0 = fmaxf(mA[m], mloc0), mn1 = fmaxf(mB[m], mloc1);
            float corr0 = __expf(mA[m] - mn0), corr1 = __expf(mB[m] - mn1);
            mA[m] = mn0; mB[m] = mn1;
            float rs0 = 0.f, rs1 = 0.f;
            #pragma unroll
            for (int nt = 0; nt < 8; nt++) {
                float p0 = __expf(cs[m][nt][0] - mn0), p1 = __expf(cs[m][nt][1] - mn0);
                float p2 = __expf(cs[m][nt][2] - mn1), p3 = __expf(cs[m][nt][3] - mn1);
                rs0 += p0 + p1; rs1 += p2 + p3;
                __half2 a = __floats2half2_rn(p0, p1);
                __half2 bb = __floats2half2_rn(p2, p3);
                plo[m][nt] = *(uint32_t*)&a;
                phi[m][nt] = *(uint32_t*)&bb;
            }
            #pragma unroll
            for (int o = 1; o <= 2; o <<= 1) {
                rs0 += __shfl_xor_sync(0xffffffffu, rs0, o);
                rs1 += __shfl_xor_sync(0xffffffffu, rs1, o);
            }
            lA[m] = lA[m] * corr0 + rs0;
            lB[m] = lB[m] * corr1 + rs1;
            #pragma unroll
            for (int nt = 0; nt < 8; nt++) {
                co[m][nt][0] *= corr0; co[m][nt][1] *= corr0;
                co[m][nt][2] *= corr1; co[m][nt][3] *= corr1;
            }
        }

        // ---- PV: plain fp16, V frags shared across both m ----
        #pragma unroll
        for (int ks = 0; ks < 4; ks++) {
            uint32_t pa0[4] = {plo[0][2 * ks], phi[0][2 * ks], plo[0][2 * ks + 1], phi[0][2 * ks + 1]};
            uint32_t pa1[4] = {plo[1][2 * ks], phi[1][2 * ks], plo[1][2 * ks + 1], phi[1][2 * ks + 1]};
            #pragma unroll
            for (int nt = 0; nt < 8; nt++) {
                int base = (hb + 8 * nt + g) * 136 + 16 * ks + 2 * t;
                uint32_t b0 = *(const uint32_t*)&smV[base];
                uint32_t b1 = *(const uint32_t*)&smV[base + 8];
                mma16(co[0][nt], pa0, b0, b1);
                mma16(co[1][nt], pa1, b0, b1);
            }
        }
    }

    // ---- epilogue ----
    float* po = g_po[split];
    #pragma unroll
    for (int m = 0; m < 2; m++) {
        int row0 = b * SEQ + i0 + rbase + 16 * m + g;
        #pragma unroll
        for (int nt = 0; nt < 8; nt++) {
            int col = hb + 8 * nt + 2 * t;
            float2 o0 = {co[m][nt][0], co[m][nt][1]};
            float2 o1 = {co[m][nt][2], co[m][nt][3]};
            *(float2*)&po[(size_t)row0 * 128 + col] = o0;
            *(float2*)&po[(size_t)(row0 + 8) * 128 + col] = o1;
        }
        if (t == 0) {
            g_pml[split][row0 * 2 + h]       = make_float2(mA[m], lA[m]);
            g_pml[split][(row0 + 8) * 2 + h] = make_float2(mB[m], lB[m]);
        }
    }
}

// ---------------- merge split-KV partials ----------------
__global__ void k_merge() {
    int idx = blockIdx.x * 256 + threadIdx.x;
    int row = idx >> 7, col = idx & 127;
    int h = col >> 6;
    float2 a = g_pml[0][row * 2 + h];
    float2 bb = g_pml[1][row * 2 + h];
    float M = fmaxf(a.x, bb.x);
    float ea = __expf(a.x - M), eb = __expf(bb.x - M);
    float l = ea * a.y + eb * bb.y;
    float o = (ea * g_po[0][idx] + eb * g_po[1][idx]) / l;
    g_attn[idx] = o;
}

// ---------------- launch ----------------
extern "C" void kernel_launch(void* const* d_in, const int* in_sizes, int n_in,
                              void* d_out, int out_size) {
    const float* x      = (const float*)d_in[0];
    const float* v_qkv  = (const float*)d_in[1];
    const float* g_qkv_ = (const float*)d_in[2];
    const float* b_qkv  = (const float*)d_in[3];
    const float* v_ff1  = (const float*)d_in[4];
    const float* g_ff1  = (const float*)d_in[5];
    const float* b_ff1  = (const float*)d_in[6];
    const float* v_ff2  = (const float*)d_in[7];
    const float* g_ff2  = (const float*)d_in[8];
    const float* b_ff2  = (const float*)d_in[9];
    float* out = (float*)d_out;

    const int GEMM_SMEM = 2 * 128 * 68 * 4;
    const int DIST_SMEM = 2 * 128 * 132 * 4;
    cudaFuncSetAttribute(k_gemm64, cudaFuncAttributeMaxDynamicSharedMemorySize, GEMM_SMEM);
    cudaFuncSetAttribute(k_dist,   cudaFuncAttributeMaxDynamicSharedMemorySize, DIST_SMEM);
    cudaFuncSetAttribute(k_flash,  cudaFuncAttributeMaxDynamicSharedMemorySize, FLASH_SMEM_BYTES);

    float* Wdev = nullptr;     cudaGetSymbolAddress((void**)&Wdev, g_W);
    float* attn_dev = nullptr; cudaGetSymbolAddress((void**)&attn_dev, g_attn);
    float* h1_dev = nullptr;   cudaGetSymbolAddress((void**)&h1_dev, g_q);

    // launch order chosen so k_dist is the 4th kernel (ncu capture slot)
    k_weights<<<640, 128>>>(v_qkv, g_qkv_, v_ff1, g_ff1, v_ff2, g_ff2);
    k_sq<<<NTOK / 8, 256>>>(x);
    k_gemm64<<<dim3(6, NTOK / 64), 256, GEMM_SMEM>>>(x, Wdev, b_qkv, nullptr, 0);
    k_dist<<<dim3(32, 32, BATCH), 256, DIST_SMEM>>>(x);
    k_flash<<<dim3(SEQ / 128, NSPLIT, BATCH), 256, FLASH_SMEM_BYTES>>>();
    k_merge<<<NTOK * DIM / 256, 256>>>();
    k_gemm64<<<dim3(2, NTOK / 64), 256, GEMM_SMEM>>>(attn_dev, Wdev + 384 * 128, b_ff1, nullptr, 1);
    k_gemm64<<<dim3(2, NTOK / 64), 256, GEMM_SMEM>>>(h1_dev, Wdev + 512 * 128, b_ff2, out, 2);
}

// round 12
// speedup vs baseline: 1.2775x; 1.2775x over previous
#include <cuda_runtime.h>
#include <cuda_fp16.h>
#include <math.h>
#include <stdint.h>

#define BATCH 2
#define SEQ   4096
#define DIM   128
#define NTOK  (BATCH * SEQ)
#define SCALE 0.125f   // 64^-0.5
#define NSPLIT 2
#define JT_PER_SPLIT (64 / NSPLIT)

// ---------------- device scratch ----------------
__device__ float  g_W[640 * 128];
__device__ float  g_q[NTOK * DIM];            // reused as h1 after flash
__device__ __half g_xh[NTOK * DIM];           // x in fp16 for dist
__device__ __half g_kh[NTOK * DIM];
__device__ __half g_kl[NTOK * DIM];
__device__ __half g_vh[(size_t)DIM * NTOK];   // V fp16, transposed [d][tok]
__device__ float  g_sq[NTOK];
__device__ __half g_dist[(size_t)BATCH * SEQ * SEQ];
__device__ double g_sum_spe;
__device__ float  g_inv2s2_spe;
__device__ float  g_spa[64 * 64];
__device__ float  g_attn[NTOK * DIM];
__device__ float  g_po[NSPLIT][NTOK * DIM];
__device__ float2 g_pml[NSPLIT][NTOK * 2];
__device__ unsigned int g_dist_ctr = 0;

// ---------------- helpers ----------------
__device__ __forceinline__ void mma16(float* c, const uint32_t* a, uint32_t b0, uint32_t b1) {
    asm volatile("mma.sync.aligned.m16n8k16.row.col.f32.f16.f16.f32 "
                 "{%0,%1,%2,%3},{%4,%5,%6,%7},{%8,%9},{%0,%1,%2,%3};"
                 : "+f"(c[0]), "+f"(c[1]), "+f"(c[2]), "+f"(c[3])
                 : "r"(a[0]), "r"(a[1]), "r"(a[2]), "r"(a[3]), "r"(b0), "r"(b1));
}

// ---------------- weight norm ----------------
__global__ void k_weights(const float* __restrict__ vq, const float* __restrict__ gq,
                          const float* __restrict__ v1, const float* __restrict__ g1,
                          const float* __restrict__ v2, const float* __restrict__ g2) {
    int r = blockIdx.x, t = threadIdx.x;
    if (r == 0 && t == 0) g_sum_spe = 0.0;
    const float* v; float g;
    if (r < 384)      { v = vq + r * 128;        g = gq[r]; }
    else if (r < 512) { v = v1 + (r - 384) * 128; g = g1[r - 384]; }
    else              { v = v2 + (r - 512) * 128; g = g2[r - 512]; }
    float val = v[t];
    float ss = val * val;
    #pragma unroll
    for (int o = 16; o; o >>= 1) ss += __shfl_xor_sync(0xffffffffu, ss, o);
    __shared__ float ws[4];
    if ((t & 31) == 0) ws[t >> 5] = ss;
    __syncthreads();
    float tot = ws[0] + ws[1] + ws[2] + ws[3];
    g_W[r * 128 + t] = val * (g / sqrtf(tot));
}

// ---------------- per-token ||x||^2 + fp16 copy of x ----------------
__global__ void k_sq(const float* __restrict__ x) {
    int token = blockIdx.x * 8 + (threadIdx.x >> 5);
    int lane  = threadIdx.x & 31;
    const float4* xp = (const float4*)(x + (size_t)token * 128);
    float4 a = xp[lane];
    // fp16 copy
    __half2 h01 = __floats2half2_rn(a.x, a.y);
    __half2 h23 = __floats2half2_rn(a.z, a.w);
    uint2 u = {*(uint32_t*)&h01, *(uint32_t*)&h23};
    *(uint2*)&g_xh[(size_t)token * 128 + lane * 4] = u;
    float ss = a.x * a.x + a.y * a.y + a.z * a.z + a.w * a.w;
    #pragma unroll
    for (int o = 16; o; o >>= 1) ss += __shfl_xor_sync(0xffffffffu, ss, o);
    if (lane == 0) g_sq[token] = ss;
}

// ---------------- tiled projection GEMM (scalar fp32, exact) ----------------
__global__ void __launch_bounds__(256) k_gemm64(const float* __restrict__ A,
                                                const float* __restrict__ Wrows,
                                                const float* __restrict__ bias,
                                                float* __restrict__ out, int mode) {
    extern __shared__ float sm[];
    float* aT = sm;
    float* wT = sm + 128 * 68;
    int c0 = blockIdx.x * 64;
    int t0 = blockIdx.y * 64;
    int tid = threadIdx.x;
    for (int idx = tid; idx < 64 * 128; idx += 256) {
        int r = idx >> 7, k = idx & 127;
        aT[k * 68 + r] = A[(t0 + r) * 128 + k];
        wT[k * 68 + r] = Wrows[(c0 + r) * 128 + k];
    }
    __syncthreads();
    int ty = tid >> 4, tx = tid & 15;
    float acc[4][4] = {};
    #pragma unroll 4
    for (int k = 0; k < 128; k++) {
        float4 av = *(const float4*)&aT[k * 68 + 4 * ty];
        float4 bv = *(const float4*)&wT[k * 68 + 4 * tx];
        float a[4] = {av.x, av.y, av.z, av.w};
        float c[4] = {bv.x, bv.y, bv.z, bv.w};
        #pragma unroll
        for (int i = 0; i < 4; i++)
            #pragma unroll
            for (int j = 0; j < 4; j++) acc[i][j] = fmaf(a[i], c[j], acc[i][j]);
    }
    #pragma unroll
    for (int i = 0; i < 4; i++) {
        int token = t0 + 4 * ty + i;
        #pragma unroll
        for (int j = 0; j < 4; j++) {
            int c = c0 + 4 * tx + j;
            float val = acc[i][j] + __ldg(&bias[c]);
            if (mode == 0) {
                if (c < 128) {
                    g_q[token * 128 + c] = val;
                } else if (c < 256) {
                    int d = c - 128;
                    __half hi = __float2half_rn(val);
                    __half lo = __float2half_rn(val - __half2float(hi));
                    g_kh[token * 128 + d] = hi;
                    g_kl[token * 128 + d] = lo;
                } else {
                    int d = c - 256;
                    g_vh[(size_t)d * NTOK + token] = __float2half_rn(val);
                }
            } else if (mode == 1) {
                g_q[token * 128 + c] = 0.5f * val * (1.0f + erff(val * 0.70710678118654752f));
            } else {
                out[token * 128 + c] = val;
            }
        }
    }
}

// ---------------- pairwise distance via fp16 MMA, finalize fused (last CTA) ----------------
// smem: xi[128][136] + xj[128][136] halves = 69632 B -> 2 CTAs/SM
#define DIST_SMEM_BYTES (2 * 128 * 136 * 2)
__global__ void __launch_bounds__(256, 2) k_dist() {
    extern __shared__ __half smh[];
    __half* xi = smh;                // [128][136]
    __half* xj = smh + 128 * 136;
    int b = blockIdx.z, i0 = blockIdx.y * 128, j0 = blockIdx.x * 128;
    int tid = threadIdx.x;
    for (int fi = tid; fi < 4096; fi += 256) {      // uint4 = 8 halves
        if (fi < 2048) {
            int r = fi >> 4, c8 = (fi & 15) * 8;
            *(uint4*)&xi[r * 136 + c8] = *(const uint4*)&g_xh[(size_t)(b * SEQ + i0 + r) * 128 + c8];
        } else {
            int v = fi - 2048, r = v >> 4, c8 = (v & 15) * 8;
            *(uint4*)&xj[r * 136 + c8] = *(const uint4*)&g_xh[(size_t)(b * SEQ + j0 + r) * 128 + c8];
        }
    }
    __syncthreads();
    int lane = tid & 31, w = tid >> 5;
    int wr = w >> 1, wc = w & 1;
    int g = lane >> 2, t = lane & 3;
    float c[2][8][4] = {};
    #pragma unroll
    for (int ks = 0; ks < 8; ks++) {
        uint32_t A[2][4];
        #pragma unroll
        for (int mt = 0; mt < 2; mt++)
            #pragma unroll
            for (int e = 0; e < 4; e++)
                A[mt][e] = *(const uint32_t*)&xi[(32 * wr + 16 * mt + g + (e & 1) * 8) * 136
                                                 + 16 * ks + 2 * t + (e >> 1) * 8];
        #pragma unroll
        for (int nt = 0; nt < 8; nt++) {
            int base = (64 * wc + 8 * nt + g) * 136 + 16 * ks + 2 * t;
            uint32_t b0 = *(const uint32_t*)&xj[base];
            uint32_t b1 = *(const uint32_t*)&xj[base + 8];
            mma16(c[0][nt], A[0], b0, b1);
            mma16(c[1][nt], A[1], b0, b1);
        }
    }
    float lsum = 0.f;
    #pragma unroll
    for (int mt = 0; mt < 2; mt++) {
        int ir0 = i0 + 32 * wr + 16 * mt + g;
        float sqi0 = __ldg(&g_sq[b * SEQ + ir0]);
        float sqi1 = __ldg(&g_sq[b * SEQ + ir0 + 8]);
        #pragma unroll
        for (int nt = 0; nt < 8; nt++) {
            int jc = j0 + 64 * wc + 8 * nt + 2 * t;
            float sj0 = __ldg(&g_sq[b * SEQ + jc]);
            float sj1 = __ldg(&g_sq[b * SEQ + jc + 1]);
            float d00 = sqrtf(fmaxf(sqi0 + sj0 - 2.f * c[mt][nt][0], 0.f));
            float d01 = sqrtf(fmaxf(sqi0 + sj1 - 2.f * c[mt][nt][1], 0.f));
            float d10 = sqrtf(fmaxf(sqi1 + sj0 - 2.f * c[mt][nt][2], 0.f));
            float d11 = sqrtf(fmaxf(sqi1 + sj1 - 2.f * c[mt][nt][3], 0.f));
            lsum += d00 + d01 + d10 + d11;
            *(__half2*)&g_dist[(size_t)(b * SEQ + ir0) * SEQ + jc]     = __floats2half2_rn(d00, d01);
            *(__half2*)&g_dist[(size_t)(b * SEQ + ir0 + 8) * SEQ + jc] = __floats2half2_rn(d10, d11);
        }
    }
    #pragma unroll
    for (int o = 16; o; o >>= 1) lsum += __shfl_xor_sync(0xffffffffu, lsum, o);
    __shared__ float rsum[8];
    if (lane == 0) rsum[w] = lsum;
    __syncthreads();
    __shared__ bool is_last;
    if (tid == 0) {
        float tot = 0.f;
        #pragma unroll
        for (int i = 0; i < 8; i++) tot += rsum[i];
        atomicAdd(&g_sum_spe, (double)tot);
        __threadfence();
        unsigned int n = gridDim.x * gridDim.y * gridDim.z;
        unsigned int cdone = atomicAdd(&g_dist_ctr, 1u);
        is_last = (cdone == n - 1);
    }
    __syncthreads();
    if (!is_last) return;

    int t2 = tid;
    __shared__ double red[256];
    double local = 0.0;
    for (int idx = t2; idx < 64 * 64; idx += 256) {
        int adx = idx >> 6, ady = idx & 63;
        double cx = adx ? 2.0 * (64 - adx) : 64.0;
        double cy = ady ? 2.0 * (64 - ady) : 64.0;
        local += cx * cy * sqrt((double)(adx * adx + ady * ady));
    }
    red[t2] = local; __syncthreads();
    for (int s = 128; s; s >>= 1) { if (t2 < s) red[t2] += red[t2 + s]; __syncthreads(); }
    __shared__ float inv_spa;
    if (t2 == 0) {
        double sig_spa = red[0] / ((double)SEQ * (double)SEQ);
        inv_spa = (float)(1.0 / (2.0 * sig_spa * sig_spa));
        double sig_spe = g_sum_spe / ((double)BATCH * (double)SEQ * (double)SEQ);
        g_inv2s2_spe = (float)(1.0 / (2.0 * sig_spe * sig_spe));
        g_dist_ctr = 0;
    }
    __syncthreads();
    float iv = inv_spa;
    for (int idx = t2; idx < 64 * 64; idx += 256) {
        int adx = idx >> 6, ady = idx & 63;
        g_spa[idx] = expf(-sqrtf((float)(adx * adx + ady * ady)) * iv);
    }
}

// ---------------- flash attention: R10 version (M=128, fp16 MMA, Q in regs) ----------------
#define WS_BYTE_OFF 69632
#define FLASH_SMEM_BYTES (WS_BYTE_OFF + 128 * 72 * 2)   // 88064
__global__ void __launch_bounds__(256, 1) k_flash() {
    extern __shared__ char smraw[];
    __half* smKH = (__half*)smraw;
    __half* smKL = smKH + 64 * 136;
    __half* smV  = smKH + 2 * 64 * 136;
    __half* smWS = (__half*)(smraw + WS_BYTE_OFF);
    int b     = blockIdx.z;
    int split = blockIdx.y;
    int i0 = blockIdx.x * 128;
    int tid = threadIdx.x;
    int lane = tid & 31, w = tid >> 5;
    int h = w >> 2, mq = w & 3;
    int g = lane >> 2, t = lane & 3;
    int hb = h * 64;
    int rbase = 32 * mq;
    float inv_spe = g_inv2s2_spe;

    uint32_t qh[2][4][4];
    #pragma unroll
    for (int m = 0; m < 2; m++)
        #pragma unroll
        for (int ks = 0; ks < 4; ks++)
            #pragma unroll
            for (int e = 0; e < 4; e++) {
                int row = i0 + rbase + 16 * m + g + (e & 1) * 8;
                int col = hb + 16 * ks + 2 * t + (e >> 1) * 8;
                float f0 = g_q[(size_t)(b * SEQ + row) * 128 + col];
                float f1 = g_q[(size_t)(b * SEQ + row) * 128 + col + 1];
                __half2 hi2 = __floats2half2_rn(f0, f1);
                qh[m][ks][e] = *(uint32_t*)&hi2;
            }

    float co[2][8][4] = {};
    float mA[2] = {-1e30f, -1e30f}, mB[2] = {-1e30f, -1e30f};
    float lA[2] = {0.f, 0.f},       lB[2] = {0.f, 0.f};

    int jt_begin = split * JT_PER_SPLIT;
    for (int jt = jt_begin; jt < jt_begin + JT_PER_SPLIT; jt++) {
        int j0 = jt * 64;
        #pragma unroll
        for (int fi = tid; fi < 3072; fi += 256) {
            if (fi < 1024) {
                int r = fi >> 4, c = fi & 15;
                *(uint4*)&smKH[r * 136 + c * 8] =
                    *(const uint4*)&g_kh[(size_t)(b * SEQ + j0 + r) * 128 + c * 8];
            } else if (fi < 2048) {
                int v = fi - 1024, r = v >> 4, c = v & 15;
                *(uint4*)&smKL[r * 136 + c * 8] =
                    *(const uint4*)&g_kl[(size_t)(b * SEQ + j0 + r) * 128 + c * 8];
            } else {
                int v = fi - 2048, d = v >> 3, c = v & 7;
                *(uint4*)&smV[d * 136 + c * 8] =
                    *(const uint4*)&g_vh[(size_t)d * NTOK + b * SEQ + j0 + c * 8];
            }
        }
        int jx = j0 >> 6;
        #pragma unroll
        for (int ii = tid; ii < 4096; ii += 256) {
            int i = ii >> 5, c2 = (ii & 31) * 2;
            __half2 d2 = *(const __half2*)&g_dist[(size_t)(b * SEQ + i0 + i) * SEQ + j0 + c2];
            float2 df = __half22float2(d2);
            int gi = i0 + i;
            int adx = abs((gi >> 6) - jx);
            int gyi = gi & 63;
            const float* spaRow = &g_spa[adx * 64];
            float w0 = spaRow[abs(gyi - c2)] * __expf(-df.x * inv_spe);
            float w1 = spaRow[abs(gyi - (c2 + 1))] * __expf(-df.y * inv_spe);
            *(__half2*)&smWS[i * 72 + c2] = __floats2half2_rn(w0, w1);
        }
        __syncthreads();

        float cs[2][8][4] = {};
        #pragma unroll
        for (int ks = 0; ks < 4; ks++) {
            #pragma unroll
            for (int nt = 0; nt < 8; nt++) {
                int base = (8 * nt + g) * 136 + hb + 16 * ks + 2 * t;
                uint32_t kh0 = *(const uint32_t*)&smKH[base];
                uint32_t kh1 = *(const uint32_t*)&smKH[base + 8];
                uint32_t kl0 = *(const uint32_t*)&smKL[base];
                uint32_t kl1 = *(const uint32_t*)&smKL[base + 8];
                mma16(cs[0][nt], qh[0][ks], kh0, kh1);
                mma16(cs[0][nt], qh[0][ks], kl0, kl1);
                mma16(cs[1][nt], qh[1][ks], kh0, kh1);
                mma16(cs[1][nt], qh[1][ks], kl0, kl1);
            }
        }

        uint32_t plo[2][8], phi[2][8];
        #pragma unroll
        for (int m = 0; m < 2; m++) {
            int r0 = rbase + 16 * m + g;
            float mloc0 = -1e30f, mloc1 = -1e30f;
            #pragma unroll
            for (int nt = 0; nt < 8; nt++) {
                int col = 8 * nt + 2 * t;
                float2 wa = __half22float2(*(const __half2*)&smWS[r0 * 72 + col]);
                float2 wb = __half22float2(*(const __half2*)&smWS[(r0 + 8) * 72 + col]);
                cs[m][nt][0] *= SCALE * wa.x; cs[m][nt][1] *= SCALE * wa.y;
                cs[m][nt][2] *= SCALE * wb.x; cs[m][nt][3] *= SCALE * wb.y;
                mloc0 = fmaxf(mloc0, fmaxf(cs[m][nt][0], cs[m][nt][1]));
                mloc1 = fmaxf(mloc1, fmaxf(cs[m][nt][2], cs[m][nt][3]));
            }
            #pragma unroll
            for (int o = 1; o <= 2; o <<= 1) {
                mloc0 = fmaxf(mloc0, __shfl_xor_sync(0xffffffffu, mloc0, o));
                mloc1 = fmaxf(mloc1, __shfl_xor_sync(0xffffffffu, mloc1, o));
            }
            float mn0 = fmaxf(mA[m], mloc0), mn1 = fmaxf(mB[m], mloc1);
            float corr0 = __expf(mA[m] - mn0), corr1 = __expf(mB[m] - mn1);
            mA[m] = mn0; mB[m] = mn1;
            float rs0 = 0.f, rs1 = 0.f;
            #pragma unroll
            for (int nt = 0; nt < 8; nt++) {
                float p0 = __expf(cs[m][nt][0] - mn0), p1 = __expf(cs[m][nt][1] - mn0);
                float p2 = __expf(cs[m][nt][2] - mn1), p3 = __expf(cs[m][nt][3] - mn1);
                rs0 += p0 + p1; rs1 += p2 + p3;
                __half2 a = __floats2half2_rn(p0, p1);
                __half2 bb = __floats2half2_rn(p2, p3);
                plo[m][nt] = *(uint32_t*)&a;
                phi[m][nt] = *(uint32_t*)&bb;
            }
            #pragma unroll
            for (int o = 1; o <= 2; o <<= 1) {
                rs0 += __shfl_xor_sync(0xffffffffu, rs0, o);
                rs1 += __shfl_xor_sync(0xffffffffu, rs1, o);
            }
            lA[m] = lA[m] * corr0 + rs0;
            lB[m] = lB[m] * corr1 + rs1;
            #pragma unroll
            for (int nt = 0; nt < 8; nt++) {
                co[m][nt][0] *= corr0; co[m][nt][1] *= corr0;
                co[m][nt][2] *= corr1; co[m][nt][3] *= corr1;
            }
        }

        #pragma unroll
        for (int ks = 0; ks < 4; ks++) {
            uint32_t pa0[4] = {plo[0][2 * ks], phi[0][2 * ks], plo[0][2 * ks + 1], phi[0][2 * ks + 1]};
            uint32_t pa1[4] = {plo[1][2 * ks], phi[1][2 * ks], plo[1][2 * ks + 1], phi[1][2 * ks + 1]};
            #pragma unroll
            for (int nt = 0; nt < 8; nt++) {
                int base = (hb + 8 * nt + g) * 136 + 16 * ks + 2 * t;
                uint32_t b0 = *(const uint32_t*)&smV[base];
                uint32_t b1 = *(const uint32_t*)&smV[base + 8];
                mma16(co[0][nt], pa0, b0, b1);
                mma16(co[1][nt], pa1, b0, b1);
            }
        }
        __syncthreads();
    }

    float* po = g_po[split];
    #pragma unroll
    for (int m = 0; m < 2; m++) {
        int row0 = b * SEQ + i0 + rbase + 16 * m + g;
        #pragma unroll
        for (int nt = 0; nt < 8; nt++) {
            int col = hb + 8 * nt + 2 * t;
            float2 o0 = {co[m][nt][0], co[m][nt][1]};
            float2 o1 = {co[m][nt][2], co[m][nt][3]};
            *(float2*)&po[(size_t)row0 * 128 + col] = o0;
            *(float2*)&po[(size_t)(row0 + 8) * 128 + col] = o1;
        }
        if (t == 0) {
            g_pml[split][row0 * 2 + h]       = make_float2(mA[m], lA[m]);
            g_pml[split][(row0 + 8) * 2 + h] = make_float2(mB[m], lB[m]);
        }
    }
}

// ---------------- merge split-KV partials ----------------
__global__ void k_merge() {
    int idx = blockIdx.x * 256 + threadIdx.x;
    int row = idx >> 7, col = idx & 127;
    int h = col >> 6;
    float2 a = g_pml[0][row * 2 + h];
    float2 bb = g_pml[1][row * 2 + h];
    float M = fmaxf(a.x, bb.x);
    float ea = __expf(a.x - M), eb = __expf(bb.x - M);
    float l = ea * a.y + eb * bb.y;
    float o = (ea * g_po[0][idx] + eb * g_po[1][idx]) / l;
    g_attn[idx] = o;
}

// ---------------- launch ----------------
extern "C" void kernel_launch(void* const* d_in, const int* in_sizes, int n_in,
                              void* d_out, int out_size) {
    const float* x      = (const float*)d_in[0];
    const float* v_qkv  = (const float*)d_in[1];
    const float* g_qkv_ = (const float*)d_in[2];
    const float* b_qkv  = (const float*)d_in[3];
    const float* v_ff1  = (const float*)d_in[4];
    const float* g_ff1  = (const float*)d_in[5];
    const float* b_ff1  = (const float*)d_in[6];
    const float* v_ff2  = (const float*)d_in[7];
    const float* g_ff2  = (const float*)d_in[8];
    const float* b_ff2  = (const float*)d_in[9];
    float* out = (float*)d_out;

    const int GEMM_SMEM = 2 * 128 * 68 * 4;
    cudaFuncSetAttribute(k_gemm64, cudaFuncAttributeMaxDynamicSharedMemorySize, GEMM_SMEM);
    cudaFuncSetAttribute(k_dist,   cudaFuncAttributeMaxDynamicSharedMemorySize, DIST_SMEM_BYTES);
    cudaFuncSetAttribute(k_flash,  cudaFuncAttributeMaxDynamicSharedMemorySize, FLASH_SMEM_BYTES);

    float* Wdev = nullptr;     cudaGetSymbolAddress((void**)&Wdev, g_W);
    float* attn_dev = nullptr; cudaGetSymbolAddress((void**)&attn_dev, g_attn);
    float* h1_dev = nullptr;   cudaGetSymbolAddress((void**)&h1_dev, g_q);

    // k_dist is 4th launch (ncu capture slot)
    k_weights<<<640, 128>>>(v_qkv, g_qkv_, v_ff1, g_ff1, v_ff2, g_ff2);
    k_sq<<<NTOK / 8, 256>>>(x);
    k_gemm64<<<dim3(6, NTOK / 64), 256, GEMM_SMEM>>>(x, Wdev, b_qkv, nullptr, 0);
    k_dist<<<dim3(32, 32, BATCH), 256, DIST_SMEM_BYTES>>>();
    k_flash<<<dim3(SEQ / 128, NSPLIT, BATCH), 256, FLASH_SMEM_BYTES>>>();
    k_merge<<<NTOK * DIM / 256, 256>>>();
    k_gemm64<<<dim3(2, NTOK / 64), 256, GEMM_SMEM>>>(attn_dev, Wdev + 384 * 128, b_ff1, nullptr, 1);
    k_gemm64<<<dim3(2, NTOK / 64), 256, GEMM_SMEM>>>(h1_dev, Wdev + 512 * 128, b_ff2, out, 2);
}

// round 13
// speedup vs baseline: 1.5132x; 1.1845x over previous
#include <cuda_runtime.h>
#include <cuda_fp16.h>
#include <math.h>
#include <stdint.h>

#define BATCH 2
#define SEQ   4096
#define DIM   128
#define NTOK  (BATCH * SEQ)
#define SCALE 0.125f   // 64^-0.5
#define NSPLIT 2
#define JT_PER_SPLIT (64 / NSPLIT)

// ---------------- device scratch ----------------
__device__ float  g_W[640 * 128];
__device__ float  g_q[NTOK * DIM];            // reused as h1 after flash
__device__ __half g_xh[NTOK * DIM];           // x in fp16 for dist
__device__ __half g_kh[NTOK * DIM];           // K fp16
__device__ __half g_vh[(size_t)DIM * NTOK];   // V fp16, transposed [d][tok]
__device__ float  g_sq[NTOK];
__device__ __half g_dist[(size_t)BATCH * SEQ * SEQ];
__device__ double g_sum_spe;
__device__ float  g_inv2s2_spe;
__device__ float  g_spa[64 * 64];
__device__ float  g_attn[NTOK * DIM];
__device__ float  g_po[NSPLIT][NTOK * DIM];
__device__ float2 g_pml[NSPLIT][NTOK * 2];
__device__ unsigned int g_dist_ctr = 0;

// ---------------- helpers ----------------
__device__ __forceinline__ void mma16(float* c, const uint32_t* a, uint32_t b0, uint32_t b1) {
    asm volatile("mma.sync.aligned.m16n8k16.row.col.f32.f16.f16.f32 "
                 "{%0,%1,%2,%3},{%4,%5,%6,%7},{%8,%9},{%0,%1,%2,%3};"
                 : "+f"(c[0]), "+f"(c[1]), "+f"(c[2]), "+f"(c[3])
                 : "r"(a[0]), "r"(a[1]), "r"(a[2]), "r"(a[3]), "r"(b0), "r"(b1));
}

// ---------------- weight norm ----------------
__global__ void k_weights(const float* __restrict__ vq, const float* __restrict__ gq,
                          const float* __restrict__ v1, const float* __restrict__ g1,
                          const float* __restrict__ v2, const float* __restrict__ g2) {
    int r = blockIdx.x, t = threadIdx.x;
    if (r == 0 && t == 0) g_sum_spe = 0.0;
    const float* v; float g;
    if (r < 384)      { v = vq + r * 128;        g = gq[r]; }
    else if (r < 512) { v = v1 + (r - 384) * 128; g = g1[r - 384]; }
    else              { v = v2 + (r - 512) * 128; g = g2[r - 512]; }
    float val = v[t];
    float ss = val * val;
    #pragma unroll
    for (int o = 16; o; o >>= 1) ss += __shfl_xor_sync(0xffffffffu, ss, o);
    __shared__ float ws[4];
    if ((t & 31) == 0) ws[t >> 5] = ss;
    __syncthreads();
    float tot = ws[0] + ws[1] + ws[2] + ws[3];
    g_W[r * 128 + t] = val * (g / sqrtf(tot));
}

// ---------------- per-token ||x||^2 + fp16 copy of x ----------------
__global__ void k_sq(const float* __restrict__ x) {
    int token = blockIdx.x * 8 + (threadIdx.x >> 5);
    int lane  = threadIdx.x & 31;
    const float4* xp = (const float4*)(x + (size_t)token * 128);
    float4 a = xp[lane];
    __half2 h01 = __floats2half2_rn(a.x, a.y);
    __half2 h23 = __floats2half2_rn(a.z, a.w);
    uint2 u = {*(uint32_t*)&h01, *(uint32_t*)&h23};
    *(uint2*)&g_xh[(size_t)token * 128 + lane * 4] = u;
    float ss = a.x * a.x + a.y * a.y + a.z * a.z + a.w * a.w;
    #pragma unroll
    for (int o = 16; o; o >>= 1) ss += __shfl_xor_sync(0xffffffffu, ss, o);
    if (lane == 0) g_sq[token] = ss;
}

// ---------------- tiled projection GEMM (scalar fp32, exact) ----------------
__global__ void __launch_bounds__(256) k_gemm64(const float* __restrict__ A,
                                                const float* __restrict__ Wrows,
                                                const float* __restrict__ bias,
                                                float* __restrict__ out, int mode) {
    extern __shared__ float sm[];
    float* aT = sm;
    float* wT = sm + 128 * 68;
    int c0 = blockIdx.x * 64;
    int t0 = blockIdx.y * 64;
    int tid = threadIdx.x;
    for (int idx = tid; idx < 64 * 128; idx += 256) {
        int r = idx >> 7, k = idx & 127;
        aT[k * 68 + r] = A[(t0 + r) * 128 + k];
        wT[k * 68 + r] = Wrows[(c0 + r) * 128 + k];
    }
    __syncthreads();
    int ty = tid >> 4, tx = tid & 15;
    float acc[4][4] = {};
    #pragma unroll 4
    for (int k = 0; k < 128; k++) {
        float4 av = *(const float4*)&aT[k * 68 + 4 * ty];
        float4 bv = *(const float4*)&wT[k * 68 + 4 * tx];
        float a[4] = {av.x, av.y, av.z, av.w};
        float c[4] = {bv.x, bv.y, bv.z, bv.w};
        #pragma unroll
        for (int i = 0; i < 4; i++)
            #pragma unroll
            for (int j = 0; j < 4; j++) acc[i][j] = fmaf(a[i], c[j], acc[i][j]);
    }
    #pragma unroll
    for (int i = 0; i < 4; i++) {
        int token = t0 + 4 * ty + i;
        #pragma unroll
        for (int j = 0; j < 4; j++) {
            int c = c0 + 4 * tx + j;
            float val = acc[i][j] + __ldg(&bias[c]);
            if (mode == 0) {
                if (c < 128) {
                    g_q[token * 128 + c] = val;
                } else if (c < 256) {
                    g_kh[token * 128 + (c - 128)] = __float2half_rn(val);
                } else {
                    g_vh[(size_t)(c - 256) * NTOK + token] = __float2half_rn(val);
                }
            } else if (mode == 1) {
                g_q[token * 128 + c] = 0.5f * val * (1.0f + erff(val * 0.70710678118654752f));
            } else {
                out[token * 128 + c] = val;
            }
        }
    }
}

// ---------------- pairwise distance via fp16 MMA, symmetric blocks only ----------------
// grid (32,32,BATCH); CTAs with bj<bi exit. Off-diag blocks write mirrored tile via smem transpose.
#define DIST_SMEM_BYTES (2 * 128 * 136 * 2)
__global__ void __launch_bounds__(256, 2) k_dist() {
    int bi = blockIdx.y, bj = blockIdx.x, b = blockIdx.z;
    if (bj < bi) return;                       // lower triangle: mirrored by upper CTA
    extern __shared__ __half smh[];
    __half* xi = smh;                // [128][136]
    __half* xj = smh + 128 * 136;
    int i0 = bi * 128, j0 = bj * 128;
    int tid = threadIdx.x;
    for (int fi = tid; fi < 4096; fi += 256) {
        if (fi < 2048) {
            int r = fi >> 4, c8 = (fi & 15) * 8;
            *(uint4*)&xi[r * 136 + c8] = *(const uint4*)&g_xh[(size_t)(b * SEQ + i0 + r) * 128 + c8];
        } else {
            int v = fi - 2048, r = v >> 4, c8 = (v & 15) * 8;
            *(uint4*)&xj[r * 136 + c8] = *(const uint4*)&g_xh[(size_t)(b * SEQ + j0 + r) * 128 + c8];
        }
    }
    __syncthreads();
    int lane = tid & 31, w = tid >> 5;
    int wr = w >> 1, wc = w & 1;
    int g = lane >> 2, t = lane & 3;
    float c[2][8][4] = {};
    #pragma unroll
    for (int ks = 0; ks < 8; ks++) {
        uint32_t A[2][4];
        #pragma unroll
        for (int mt = 0; mt < 2; mt++)
            #pragma unroll
            for (int e = 0; e < 4; e++)
                A[mt][e] = *(const uint32_t*)&xi[(32 * wr + 16 * mt + g + (e & 1) * 8) * 136
                                                 + 16 * ks + 2 * t + (e >> 1) * 8];
        #pragma unroll
        for (int nt = 0; nt < 8; nt++) {
            int base = (64 * wc + 8 * nt + g) * 136 + 16 * ks + 2 * t;
            uint32_t b0 = *(const uint32_t*)&xj[base];
            uint32_t b1 = *(const uint32_t*)&xj[base + 8];
            mma16(c[0][nt], A[0], b0, b1);
            mma16(c[1][nt], A[1], b0, b1);
        }
    }
    bool diag = (bi == bj);
    __syncthreads();                 // all MMA reads of xi done before staging reuse
    __half* sT = xi;                 // staging for transposed tile [j_local][136]

    float lsum = 0.f;
    #pragma unroll
    for (int mt = 0; mt < 2; mt++) {
        int irl = 32 * wr + 16 * mt + g;
        int ir0 = i0 + irl;
        float sqi0 = __ldg(&g_sq[b * SEQ + ir0]);
        float sqi1 = __ldg(&g_sq[b * SEQ + ir0 + 8]);
        #pragma unroll
        for (int nt = 0; nt < 8; nt++) {
            int jcl = 64 * wc + 8 * nt + 2 * t;
            int jc = j0 + jcl;
            float sj0 = __ldg(&g_sq[b * SEQ + jc]);
            float sj1 = __ldg(&g_sq[b * SEQ + jc + 1]);
            float d00 = sqrtf(fmaxf(sqi0 + sj0 - 2.f * c[mt][nt][0], 0.f));
            float d01 = sqrtf(fmaxf(sqi0 + sj1 - 2.f * c[mt][nt][1], 0.f));
            float d10 = sqrtf(fmaxf(sqi1 + sj0 - 2.f * c[mt][nt][2], 0.f));
            float d11 = sqrtf(fmaxf(sqi1 + sj1 - 2.f * c[mt][nt][3], 0.f));
            lsum += d00 + d01 + d10 + d11;
            __half2 p0 = __floats2half2_rn(d00, d01);
            __half2 p1 = __floats2half2_rn(d10, d11);
            *(__half2*)&g_dist[(size_t)(b * SEQ + ir0) * SEQ + jc]     = p0;
            *(__half2*)&g_dist[(size_t)(b * SEQ + ir0 + 8) * SEQ + jc] = p1;
            if (!diag) {
                sT[jcl * 136 + irl]           = __low2half(p0);
                sT[(jcl + 1) * 136 + irl]     = __high2half(p0);
                sT[jcl * 136 + irl + 8]       = __low2half(p1);
                sT[(jcl + 1) * 136 + irl + 8] = __high2half(p1);
            }
        }
    }
    if (!diag) {
        __syncthreads();
        // coalesced mirrored write: g_dist[(j0+jl)][i0..i0+127]
        for (int fi = tid; fi < 2048; fi += 256) {
            int jl = fi >> 4, c8 = (fi & 15) * 8;
            *(uint4*)&g_dist[(size_t)(b * SEQ + j0 + jl) * SEQ + i0 + c8] =
                *(const uint4*)&sT[jl * 136 + c8];
        }
    }
    #pragma unroll
    for (int o = 16; o; o >>= 1) lsum += __shfl_xor_sync(0xffffffffu, lsum, o);
    __shared__ float rsum[8];
    if (lane == 0) rsum[w] = lsum;
    __syncthreads();
    __shared__ bool is_last;
    if (tid == 0) {
        float tot = 0.f;
        #pragma unroll
        for (int i = 0; i < 8; i++) tot += rsum[i];
        atomicAdd(&g_sum_spe, (double)(diag ? tot : 2.f * tot));
        __threadfence();
        unsigned int nwork = (32 * 33 / 2) * gridDim.z;   // working CTAs only
        unsigned int cdone = atomicAdd(&g_dist_ctr, 1u);
        is_last = (cdone == nwork - 1);
    }
    __syncthreads();
    if (!is_last) return;

    int t2 = tid;
    __shared__ double red[256];
    double local = 0.0;
    for (int idx = t2; idx < 64 * 64; idx += 256) {
        int adx = idx >> 6, ady = idx & 63;
        double cx = adx ? 2.0 * (64 - adx) : 64.0;
        double cy = ady ? 2.0 * (64 - ady) : 64.0;
        local += cx * cy * sqrt((double)(adx * adx + ady * ady));
    }
    red[t2] = local; __syncthreads();
    for (int s = 128; s; s >>= 1) { if (t2 < s) red[t2] += red[t2 + s]; __syncthreads(); }
    __shared__ float inv_spa;
    if (t2 == 0) {
        double sig_spa = red[0] / ((double)SEQ * (double)SEQ);
        inv_spa = (float)(1.0 / (2.0 * sig_spa * sig_spa));
        double sig_spe = g_sum_spe / ((double)BATCH * (double)SEQ * (double)SEQ);
        g_inv2s2_spe = (float)(1.0 / (2.0 * sig_spe * sig_spe));
        g_dist_ctr = 0;
    }
    __syncthreads();
    float iv = inv_spa;
    for (int idx = t2; idx < 64 * 64; idx += 256) {
        int adx = idx >> 6, ady = idx & 63;
        g_spa[idx] = expf(-sqrtf((float)(adx * adx + ady * ady)) * iv);
    }
}

// ---------------- flash attention: M=128, fp16 MMA 1-term QK, split-KV ----------------
// smem halves: KH[64][136]@0, V[128][136]@8704, WS[128][72]@26112 -> 70656 B
#define FL_V_HOFF  8704
#define FL_WS_HOFF 26112
#define FLASH_SMEM_BYTES ((FL_WS_HOFF + 128 * 72) * 2)
__global__ void __launch_bounds__(256, 1) k_flash() {
    extern __shared__ __half smh[];
    __half* smKH = smh;
    __half* smV  = smh + FL_V_HOFF;
    __half* smWS = smh + FL_WS_HOFF;
    int b     = blockIdx.z;
    int split = blockIdx.y;
    int i0 = blockIdx.x * 128;
    int tid = threadIdx.x;
    int lane = tid & 31, w = tid >> 5;
    int h = w >> 2, mq = w & 3;
    int g = lane >> 2, t = lane & 3;
    int hb = h * 64;
    int rbase = 32 * mq;
    float inv_spe = g_inv2s2_spe;

    uint32_t qh[2][4][4];
    #pragma unroll
    for (int m = 0; m < 2; m++)
        #pragma unroll
        for (int ks = 0; ks < 4; ks++)
            #pragma unroll
            for (int e = 0; e < 4; e++) {
                int row = i0 + rbase + 16 * m + g + (e & 1) * 8;
                int col = hb + 16 * ks + 2 * t + (e >> 1) * 8;
                float f0 = g_q[(size_t)(b * SEQ + row) * 128 + col];
                float f1 = g_q[(size_t)(b * SEQ + row) * 128 + col + 1];
                __half2 hi2 = __floats2half2_rn(f0, f1);
                qh[m][ks][e] = *(uint32_t*)&hi2;
            }

    float co[2][8][4] = {};
    float mA[2] = {-1e30f, -1e30f}, mB[2] = {-1e30f, -1e30f};
    float lA[2] = {0.f, 0.f},       lB[2] = {0.f, 0.f};

    int jt_begin = split * JT_PER_SPLIT;
    for (int jt = jt_begin; jt < jt_begin + JT_PER_SPLIT; jt++) {
        int j0 = jt * 64;
        #pragma unroll
        for (int fi = tid; fi < 2048; fi += 256) {
            if (fi < 1024) {
                int r = fi >> 4, c = fi & 15;
                *(uint4*)&smKH[r * 136 + c * 8] =
                    *(const uint4*)&g_kh[(size_t)(b * SEQ + j0 + r) * 128 + c * 8];
            } else {
                int v = fi - 1024, d = v >> 3, c = v & 7;
                *(uint4*)&smV[d * 136 + c * 8] =
                    *(const uint4*)&g_vh[(size_t)d * NTOK + b * SEQ + j0 + c * 8];
            }
        }
        int jx = j0 >> 6;
        #pragma unroll
        for (int ii = tid; ii < 4096; ii += 256) {
            int i = ii >> 5, c2 = (ii & 31) * 2;
            __half2 d2 = *(const __half2*)&g_dist[(size_t)(b * SEQ + i0 + i) * SEQ + j0 + c2];
            float2 df = __half22float2(d2);
            int gi = i0 + i;
            int adx = abs((gi >> 6) - jx);
            int gyi = gi & 63;
            const float* spaRow = &g_spa[adx * 64];
            float w0 = spaRow[abs(gyi - c2)] * __expf(-df.x * inv_spe);
            float w1 = spaRow[abs(gyi - (c2 + 1))] * __expf(-df.y * inv_spe);
            *(__half2*)&smWS[i * 72 + c2] = __floats2half2_rn(w0, w1);
        }
        __syncthreads();

        // ---- QK^T: 1-term fp16 ----
        float cs[2][8][4] = {};
        #pragma unroll
        for (int ks = 0; ks < 4; ks++) {
            #pragma unroll
            for (int nt = 0; nt < 8; nt++) {
                int base = (8 * nt + g) * 136 + hb + 16 * ks + 2 * t;
                uint32_t kh0 = *(const uint32_t*)&smKH[base];
                uint32_t kh1 = *(const uint32_t*)&smKH[base + 8];
                mma16(cs[0][nt], qh[0][ks], kh0, kh1);
                mma16(cs[1][nt], qh[1][ks], kh0, kh1);
            }
        }

        uint32_t plo[2][8], phi[2][8];
        #pragma unroll
        for (int m = 0; m < 2; m++) {
            int r0 = rbase + 16 * m + g;
            float mloc0 = -1e30f, mloc1 = -1e30f;
            #pragma unroll
            for (int nt = 0; nt < 8; nt++) {
                int col = 8 * nt + 2 * t;
                float2 wa = __half22float2(*(const __half2*)&smWS[r0 * 72 + col]);
                float2 wb = __half22float2(*(const __half2*)&smWS[(r0 + 8) * 72 + col]);
                cs[m][nt][0] *= SCALE * wa.x; cs[m][nt][1] *= SCALE * wa.y;
                cs[m][nt][2] *= SCALE * wb.x; cs[m][nt][3] *= SCALE * wb.y;
                mloc0 = fmaxf(mloc0, fmaxf(cs[m][nt][0], cs[m][nt][1]));
                mloc1 = fmaxf(mloc1, fmaxf(cs[m][nt][2], cs[m][nt][3]));
            }
            #pragma unroll
            for (int o = 1; o <= 2; o <<= 1) {
                mloc0 = fmaxf(mloc0, __shfl_xor_sync(0xffffffffu, mloc0, o));
                mloc1 = fmaxf(mloc1, __shfl_xor_sync(0xffffffffu, mloc1, o));
            }
            float mn0 = fmaxf(mA[m], mloc0), mn1 = fmaxf(mB[m], mloc1);
            float corr0 = __expf(mA[m] - mn0), corr1 = __expf(mB[m] - mn1);
            mA[m] = mn0; mB[m] = mn1;
            float rs0 = 0.f, rs1 = 0.f;
            #pragma unroll
            for (int nt = 0; nt < 8; nt++) {
                float p0 = __expf(cs[m][nt][0] - mn0), p1 = __expf(cs[m][nt][1] - mn0);
                float p2 = __expf(cs[m][nt][2] - mn1), p3 = __expf(cs[m][nt][3] - mn1);
                rs0 += p0 + p1; rs1 += p2 + p3;
                __half2 a = __floats2half2_rn(p0, p1);
                __half2 bb = __floats2half2_rn(p2, p3);
                plo[m][nt] = *(uint32_t*)&a;
                phi[m][nt] = *(uint32_t*)&bb;
            }
            #pragma unroll
            for (int o = 1; o <= 2; o <<= 1) {
                rs0 += __shfl_xor_sync(0xffffffffu, rs0, o);
                rs1 += __shfl_xor_sync(0xffffffffu, rs1, o);
            }
            lA[m] = lA[m] * corr0 + rs0;
            lB[m] = lB[m] * corr1 + rs1;
            #pragma unroll
            for (int nt = 0; nt < 8; nt++) {
                co[m][nt][0] *= corr0; co[m][nt][1] *= corr0;
                co[m][nt][2] *= corr1; co[m][nt][3] *= corr1;
            }
        }

        #pragma unroll
        for (int ks = 0; ks < 4; ks++) {
            uint32_t pa0[4] = {plo[0][2 * ks], phi[0][2 * ks], plo[0][2 * ks + 1], phi[0][2 * ks + 1]};
            uint32_t pa1[4] = {plo[1][2 * ks], phi[1][2 * ks], plo[1][2 * ks + 1], phi[1][2 * ks + 1]};
            #pragma unroll
            for (int nt = 0; nt < 8; nt++) {
                int base = (hb + 8 * nt + g) * 136 + 16 * ks + 2 * t;
                uint32_t b0 = *(const uint32_t*)&smV[base];
                uint32_t b1 = *(const uint32_t*)&smV[base + 8];
                mma16(co[0][nt], pa0, b0, b1);
                mma16(co[1][nt], pa1, b0, b1);
            }
        }
        __syncthreads();
    }

    float* po = g_po[split];
    #pragma unroll
    for (int m = 0; m < 2; m++) {
        int row0 = b * SEQ + i0 + rbase + 16 * m + g;
        #pragma unroll
        for (int nt = 0; nt < 8; nt++) {
            int col = hb + 8 * nt + 2 * t;
            float2 o0 = {co[m][nt][0], co[m][nt][1]};
            float2 o1 = {co[m][nt][2], co[m][nt][3]};
            *(float2*)&po[(size_t)row0 * 128 + col] = o0;
            *(float2*)&po[(size_t)(row0 + 8) * 128 + col] = o1;
        }
        if (t == 0) {
            g_pml[split][row0 * 2 + h]       = make_float2(mA[m], lA[m]);
            g_pml[split][(row0 + 8) * 2 + h] = make_float2(mB[m], lB[m]);
        }
    }
}

// ---------------- merge split-KV partials ----------------
__global__ void k_merge() {
    int idx = blockIdx.x * 256 + threadIdx.x;
    int row = idx >> 7, col = idx & 127;
    int h = col >> 6;
    float2 a = g_pml[0][row * 2 + h];
    float2 bb = g_pml[1][row * 2 + h];
    float M = fmaxf(a.x, bb.x);
    float ea = __expf(a.x - M), eb = __expf(bb.x - M);
    float l = ea * a.y + eb * bb.y;
    float o = (ea * g_po[0][idx] + eb * g_po[1][idx]) / l;
    g_attn[idx] = o;
}

// ---------------- launch ----------------
extern "C" void kernel_launch(void* const* d_in, const int* in_sizes, int n_in,
                              void* d_out, int out_size) {
    const float* x      = (const float*)d_in[0];
    const float* v_qkv  = (const float*)d_in[1];
    const float* g_qkv_ = (const float*)d_in[2];
    const float* b_qkv  = (const float*)d_in[3];
    const float* v_ff1  = (const float*)d_in[4];
    const float* g_ff1  = (const float*)d_in[5];
    const float* b_ff1  = (const float*)d_in[6];
    const float* v_ff2  = (const float*)d_in[7];
    const float* g_ff2  = (const float*)d_in[8];
    const float* b_ff2  = (const float*)d_in[9];
    float* out = (float*)d_out;

    const int GEMM_SMEM = 2 * 128 * 68 * 4;
    cudaFuncSetAttribute(k_gemm64, cudaFuncAttributeMaxDynamicSharedMemorySize, GEMM_SMEM);
    cudaFuncSetAttribute(k_dist,   cudaFuncAttributeMaxDynamicSharedMemorySize, DIST_SMEM_BYTES);
    cudaFuncSetAttribute(k_flash,  cudaFuncAttributeMaxDynamicSharedMemorySize, FLASH_SMEM_BYTES);

    float* Wdev = nullptr;     cudaGetSymbolAddress((void**)&Wdev, g_W);
    float* attn_dev = nullptr; cudaGetSymbolAddress((void**)&attn_dev, g_attn);
    float* h1_dev = nullptr;   cudaGetSymbolAddress((void**)&h1_dev, g_q);

    // k_dist is 4th launch (ncu capture slot)
    k_weights<<<640, 128>>>(v_qkv, g_qkv_, v_ff1, g_ff1, v_ff2, g_ff2);
    k_sq<<<NTOK / 8, 256>>>(x);
    k_gemm64<<<dim3(6, NTOK / 64), 256, GEMM_SMEM>>>(x, Wdev, b_qkv, nullptr, 0);
    k_dist<<<dim3(32, 32, BATCH), 256, DIST_SMEM_BYTES>>>();
    k_flash<<<dim3(SEQ / 128, NSPLIT, BATCH), 256, FLASH_SMEM_BYTES>>>();
    k_merge<<<NTOK * DIM / 256, 256>>>();
    k_gemm64<<<dim3(2, NTOK / 64), 256, GEMM_SMEM>>>(attn_dev, Wdev + 384 * 128, b_ff1, nullptr, 1);
    k_gemm64<<<dim3(2, NTOK / 64), 256, GEMM_SMEM>>>(h1_dev, Wdev + 512 * 128, b_ff2, out, 2);
}

// round 14
// speedup vs baseline: 1.5815x; 1.0451x over previous
#include <cuda_runtime.h>
#include <cuda_fp16.h>
#include <math.h>
#include <stdint.h>

#define BATCH 2
#define SEQ   4096
#define DIM   128
#define NTOK  (BATCH * SEQ)
#define SCALE 0.125f   // 64^-0.5
#define NSPLIT 2
#define JT_PER_SPLIT (64 / NSPLIT)

// ---------------- device scratch ----------------
__device__ float  g_W[640 * 128];
__device__ float  g_q[NTOK * DIM];            // reused as h1 after flash
__device__ __half g_xh[NTOK * DIM];           // x in fp16 for dist
__device__ __half g_kh[NTOK * DIM];           // K fp16
__device__ __half g_vh[(size_t)DIM * NTOK];   // V fp16, transposed [d][tok]
__device__ float  g_sq[NTOK];
__device__ __half g_dist[(size_t)BATCH * SEQ * SEQ];
__device__ double g_sum_spe;
__device__ float  g_inv2s2_spe;
__device__ float  g_spa[64 * 64];
__device__ float  g_attn[NTOK * DIM];
__device__ float  g_po[NSPLIT][NTOK * DIM];
__device__ float2 g_pml[NSPLIT][NTOK * 2];
__device__ unsigned int g_dist_ctr = 0;

// ---------------- helpers ----------------
__device__ __forceinline__ void mma16(float* c, const uint32_t* a, uint32_t b0, uint32_t b1) {
    asm volatile("mma.sync.aligned.m16n8k16.row.col.f32.f16.f16.f32 "
                 "{%0,%1,%2,%3},{%4,%5,%6,%7},{%8,%9},{%0,%1,%2,%3};"
                 : "+f"(c[0]), "+f"(c[1]), "+f"(c[2]), "+f"(c[3])
                 : "r"(a[0]), "r"(a[1]), "r"(a[2]), "r"(a[3]), "r"(b0), "r"(b1));
}
__device__ __forceinline__ void split_h(float v, __half& hi, __half& lo) {
    hi = __float2half_rn(v);
    lo = __float2half_rn(v - __half2float(hi));
}

// ---------------- weight norm + init + ||x||^2 + x fp16 copy (fused) ----------------
// blocks 0..639: weights; blocks 640..: 4 tokens per block
__global__ void k_weights_sq(const float* __restrict__ vq, const float* __restrict__ gq,
                             const float* __restrict__ v1, const float* __restrict__ g1,
                             const float* __restrict__ v2, const float* __restrict__ g2,
                             const float* __restrict__ x) {
    int blk = blockIdx.x, t = threadIdx.x;
    if (blk >= 640) {
        int token = (blk - 640) * 4 + (t >> 5);
        int lane = t & 31;
        const float4* xp = (const float4*)(x + (size_t)token * 128);
        float4 a = xp[lane];
        __half2 h01 = __floats2half2_rn(a.x, a.y);
        __half2 h23 = __floats2half2_rn(a.z, a.w);
        uint2 u = {*(uint32_t*)&h01, *(uint32_t*)&h23};
        *(uint2*)&g_xh[(size_t)token * 128 + lane * 4] = u;
        float ss = a.x * a.x + a.y * a.y + a.z * a.z + a.w * a.w;
        #pragma unroll
        for (int o = 16; o; o >>= 1) ss += __shfl_xor_sync(0xffffffffu, ss, o);
        if (lane == 0) g_sq[token] = ss;
        return;
    }
    if (blk == 0 && t == 0) g_sum_spe = 0.0;
    int r = blk;
    const float* v; float g;
    if (r < 384)      { v = vq + r * 128;        g = gq[r]; }
    else if (r < 512) { v = v1 + (r - 384) * 128; g = g1[r - 384]; }
    else              { v = v2 + (r - 512) * 128; g = g2[r - 512]; }
    float val = v[t];
    float ss = val * val;
    #pragma unroll
    for (int o = 16; o; o >>= 1) ss += __shfl_xor_sync(0xffffffffu, ss, o);
    __shared__ float ws[4];
    if ((t & 31) == 0) ws[t >> 5] = ss;
    __syncthreads();
    float tot = ws[0] + ws[1] + ws[2] + ws[3];
    g_W[r * 128 + t] = val * (g / sqrtf(tot));
}

// ---------------- projection GEMM via fp16 MMA (A 2-term hi/lo, W hi) ----------------
// 128 tokens x 128 cols per CTA. smem: ah/al/wh [128][136] halves = 104448 B
#define PG_SMEM_BYTES (3 * 128 * 136 * 2)
__global__ void __launch_bounds__(256, 1) k_gemm128(const float* __restrict__ A,
                                                    const float* __restrict__ Wrows,
                                                    const float* __restrict__ bias,
                                                    float* __restrict__ out, int mode) {
    extern __shared__ __half smh[];
    __half* ah = smh;
    __half* al = smh + 128 * 136;
    __half* wh = smh + 2 * 128 * 136;
    int c0 = blockIdx.x * 128;
    int t0 = blockIdx.y * 128;
    int tid = threadIdx.x;
    for (int fi = tid; fi < 8192; fi += 256) {
        if (fi < 4096) {
            int r = fi >> 5, c4 = (fi & 31) * 4;
            float4 a = *(const float4*)&A[(size_t)(t0 + r) * 128 + c4];
            __half h0, l0, h1, l1, h2, l2, h3, l3;
            split_h(a.x, h0, l0); split_h(a.y, h1, l1);
            split_h(a.z, h2, l2); split_h(a.w, h3, l3);
            __half2 hh0 = __halves2half2(h0, h1), hh1 = __halves2half2(h2, h3);
            __half2 ll0 = __halves2half2(l0, l1), ll1 = __halves2half2(l2, l3);
            uint2 uh = {*(uint32_t*)&hh0, *(uint32_t*)&hh1};
            uint2 ul = {*(uint32_t*)&ll0, *(uint32_t*)&ll1};
            *(uint2*)&ah[r * 136 + c4] = uh;
            *(uint2*)&al[r * 136 + c4] = ul;
        } else {
            int v = fi - 4096, r = v >> 5, c4 = (v & 31) * 4;
            float4 wv = *(const float4*)&Wrows[(size_t)(c0 + r) * 128 + c4];
            __half2 hh0 = __floats2half2_rn(wv.x, wv.y);
            __half2 hh1 = __floats2half2_rn(wv.z, wv.w);
            uint2 uh = {*(uint32_t*)&hh0, *(uint32_t*)&hh1};
            *(uint2*)&wh[r * 136 + c4] = uh;
        }
    }
    __syncthreads();
    int lane = tid & 31, w = tid >> 5;
    int wr = w >> 1, wc = w & 1;
    int g = lane >> 2, t = lane & 3;
    float c[2][8][4] = {};
    #pragma unroll
    for (int ks = 0; ks < 8; ks++) {
        uint32_t Ah[2][4], Al[2][4];
        #pragma unroll
        for (int mt = 0; mt < 2; mt++)
            #pragma unroll
            for (int e = 0; e < 4; e++) {
                int idx = (32 * wr + 16 * mt + g + (e & 1) * 8) * 136
                          + 16 * ks + 2 * t + (e >> 1) * 8;
                Ah[mt][e] = *(const uint32_t*)&ah[idx];
                Al[mt][e] = *(const uint32_t*)&al[idx];
            }
        #pragma unroll
        for (int nt = 0; nt < 8; nt++) {
            int base = (64 * wc + 8 * nt + g) * 136 + 16 * ks + 2 * t;
            uint32_t b0 = *(const uint32_t*)&wh[base];
            uint32_t b1 = *(const uint32_t*)&wh[base + 8];
            mma16(c[0][nt], Ah[0], b0, b1);
            mma16(c[0][nt], Al[0], b0, b1);
            mma16(c[1][nt], Ah[1], b0, b1);
            mma16(c[1][nt], Al[1], b0, b1);
        }
    }
    // epilogue
    #pragma unroll
    for (int mt = 0; mt < 2; mt++) {
        int irl = 32 * wr + 16 * mt + g;
        int token = t0 + irl;
        #pragma unroll
        for (int nt = 0; nt < 8; nt++) {
            int jcl = 64 * wc + 8 * nt + 2 * t;
            int col = c0 + jcl;
            float bb0 = __ldg(&bias[col]), bb1 = __ldg(&bias[col + 1]);
            float v0 = c[mt][nt][0] + bb0, v1 = c[mt][nt][1] + bb1;
            float v2 = c[mt][nt][2] + bb0, v3 = c[mt][nt][3] + bb1;
            if (mode == 0) {
                if (col < 128) {
                    *(float2*)&g_q[(size_t)token * 128 + col]       = make_float2(v0, v1);
                    *(float2*)&g_q[(size_t)(token + 8) * 128 + col] = make_float2(v2, v3);
                } else if (col < 256) {
                    int d = col - 128;
                    *(__half2*)&g_kh[(size_t)token * 128 + d]       = __floats2half2_rn(v0, v1);
                    *(__half2*)&g_kh[(size_t)(token + 8) * 128 + d] = __floats2half2_rn(v2, v3);
                } else {
                    int d = col - 256;
                    g_vh[(size_t)d * NTOK + token]           = __float2half_rn(v0);
                    g_vh[(size_t)(d + 1) * NTOK + token]     = __float2half_rn(v1);
                    g_vh[(size_t)d * NTOK + token + 8]       = __float2half_rn(v2);
                    g_vh[(size_t)(d + 1) * NTOK + token + 8] = __float2half_rn(v3);
                }
            } else if (mode == 1) {
                g_q[(size_t)token * 128 + col]           = 0.5f * v0 * (1.0f + erff(v0 * 0.70710678118654752f));
                g_q[(size_t)token * 128 + col + 1]       = 0.5f * v1 * (1.0f + erff(v1 * 0.70710678118654752f));
                g_q[(size_t)(token + 8) * 128 + col]     = 0.5f * v2 * (1.0f + erff(v2 * 0.70710678118654752f));
                g_q[(size_t)(token + 8) * 128 + col + 1] = 0.5f * v3 * (1.0f + erff(v3 * 0.70710678118654752f));
            } else {
                *(float2*)&out[(size_t)token * 128 + col]       = make_float2(v0, v1);
                *(float2*)&out[(size_t)(token + 8) * 128 + col] = make_float2(v2, v3);
            }
        }
    }
}

// ---------------- pairwise distance via fp16 MMA, symmetric blocks only ----------------
#define DIST_SMEM_BYTES (2 * 128 * 136 * 2)
__global__ void __launch_bounds__(256, 2) k_dist() {
    int bi = blockIdx.y, bj = blockIdx.x, b = blockIdx.z;
    if (bj < bi) return;
    extern __shared__ __half smh[];
    __half* xi = smh;                // [128][136]
    __half* xj = smh + 128 * 136;
    int i0 = bi * 128, j0 = bj * 128;
    int tid = threadIdx.x;
    for (int fi = tid; fi < 4096; fi += 256) {
        if (fi < 2048) {
            int r = fi >> 4, c8 = (fi & 15) * 8;
            *(uint4*)&xi[r * 136 + c8] = *(const uint4*)&g_xh[(size_t)(b * SEQ + i0 + r) * 128 + c8];
        } else {
            int v = fi - 2048, r = v >> 4, c8 = (v & 15) * 8;
            *(uint4*)&xj[r * 136 + c8] = *(const uint4*)&g_xh[(size_t)(b * SEQ + j0 + r) * 128 + c8];
        }
    }
    __syncthreads();
    int lane = tid & 31, w = tid >> 5;
    int wr = w >> 1, wc = w & 1;
    int g = lane >> 2, t = lane & 3;
    float c[2][8][4] = {};
    #pragma unroll
    for (int ks = 0; ks < 8; ks++) {
        uint32_t A[2][4];
        #pragma unroll
        for (int mt = 0; mt < 2; mt++)
            #pragma unroll
            for (int e = 0; e < 4; e++)
                A[mt][e] = *(const uint32_t*)&xi[(32 * wr + 16 * mt + g + (e & 1) * 8) * 136
                                                 + 16 * ks + 2 * t + (e >> 1) * 8];
        #pragma unroll
        for (int nt = 0; nt < 8; nt++) {
            int base = (64 * wc + 8 * nt + g) * 136 + 16 * ks + 2 * t;
            uint32_t b0 = *(const uint32_t*)&xj[base];
            uint32_t b1 = *(const uint32_t*)&xj[base + 8];
            mma16(c[0][nt], A[0], b0, b1);
            mma16(c[1][nt], A[1], b0, b1);
        }
    }
    bool diag = (bi == bj);
    __syncthreads();
    __half* sT = xi;

    float lsum = 0.f;
    #pragma unroll
    for (int mt = 0; mt < 2; mt++) {
        int irl = 32 * wr + 16 * mt + g;
        int ir0 = i0 + irl;
        float sqi0 = __ldg(&g_sq[b * SEQ + ir0]);
        float sqi1 = __ldg(&g_sq[b * SEQ + ir0 + 8]);
        #pragma unroll
        for (int nt = 0; nt < 8; nt++) {
            int jcl = 64 * wc + 8 * nt + 2 * t;
            int jc = j0 + jcl;
            float sj0 = __ldg(&g_sq[b * SEQ + jc]);
            float sj1 = __ldg(&g_sq[b * SEQ + jc + 1]);
            float d00 = sqrtf(fmaxf(sqi0 + sj0 - 2.f * c[mt][nt][0], 0.f));
            float d01 = sqrtf(fmaxf(sqi0 + sj1 - 2.f * c[mt][nt][1], 0.f));
            float d10 = sqrtf(fmaxf(sqi1 + sj0 - 2.f * c[mt][nt][2], 0.f));
            float d11 = sqrtf(fmaxf(sqi1 + sj1 - 2.f * c[mt][nt][3], 0.f));
            lsum += d00 + d01 + d10 + d11;
            __half2 p0 = __floats2half2_rn(d00, d01);
            __half2 p1 = __floats2half2_rn(d10, d11);
            *(__half2*)&g_dist[(size_t)(b * SEQ + ir0) * SEQ + jc]     = p0;
            *(__half2*)&g_dist[(size_t)(b * SEQ + ir0 + 8) * SEQ + jc] = p1;
            if (!diag) {
                sT[jcl * 136 + irl]           = __low2half(p0);
                sT[(jcl + 1) * 136 + irl]     = __high2half(p0);
                sT[jcl * 136 + irl + 8]       = __low2half(p1);
                sT[(jcl + 1) * 136 + irl + 8] = __high2half(p1);
            }
        }
    }
    if (!diag) {
        __syncthreads();
        for (int fi = tid; fi < 2048; fi += 256) {
            int jl = fi >> 4, c8 = (fi & 15) * 8;
            *(uint4*)&g_dist[(size_t)(b * SEQ + j0 + jl) * SEQ + i0 + c8] =
                *(const uint4*)&sT[jl * 136 + c8];
        }
    }
    #pragma unroll
    for (int o = 16; o; o >>= 1) lsum += __shfl_xor_sync(0xffffffffu, lsum, o);
    __shared__ float rsum[8];
    if (lane == 0) rsum[w] = lsum;
    __syncthreads();
    __shared__ bool is_last;
    if (tid == 0) {
        float tot = 0.f;
        #pragma unroll
        for (int i = 0; i < 8; i++) tot += rsum[i];
        atomicAdd(&g_sum_spe, (double)(diag ? tot : 2.f * tot));
        __threadfence();
        unsigned int nwork = (32 * 33 / 2) * gridDim.z;
        unsigned int cdone = atomicAdd(&g_dist_ctr, 1u);
        is_last = (cdone == nwork - 1);
    }
    __syncthreads();
    if (!is_last) return;

    int t2 = tid;
    __shared__ double red[256];
    double local = 0.0;
    for (int idx = t2; idx < 64 * 64; idx += 256) {
        int adx = idx >> 6, ady = idx & 63;
        double cx = adx ? 2.0 * (64 - adx) : 64.0;
        double cy = ady ? 2.0 * (64 - ady) : 64.0;
        local += cx * cy * sqrt((double)(adx * adx + ady * ady));
    }
    red[t2] = local; __syncthreads();
    for (int s = 128; s; s >>= 1) { if (t2 < s) red[t2] += red[t2 + s]; __syncthreads(); }
    __shared__ float inv_spa;
    if (t2 == 0) {
        double sig_spa = red[0] / ((double)SEQ * (double)SEQ);
        inv_spa = (float)(1.0 / (2.0 * sig_spa * sig_spa));
        double sig_spe = g_sum_spe / ((double)BATCH * (double)SEQ * (double)SEQ);
        g_inv2s2_spe = (float)(1.0 / (2.0 * sig_spe * sig_spe));
        g_dist_ctr = 0;
    }
    __syncthreads();
    float iv = inv_spa;
    for (int idx = t2; idx < 64 * 64; idx += 256) {
        int adx = idx >> 6, ady = idx & 63;
        g_spa[idx] = expf(-sqrtf((float)(adx * adx + ady * ady)) * iv);
    }
}

// ---------------- flash attention: M=128, fp16 MMA 1-term QK, split-KV ----------------
#define FL_V_HOFF  8704
#define FL_WS_HOFF 26112
#define FLASH_SMEM_BYTES ((FL_WS_HOFF + 128 * 72) * 2)
__global__ void __launch_bounds__(256, 1) k_flash() {
    extern __shared__ __half smh[];
    __half* smKH = smh;
    __half* smV  = smh + FL_V_HOFF;
    __half* smWS = smh + FL_WS_HOFF;
    int b     = blockIdx.z;
    int split = blockIdx.y;
    int i0 = blockIdx.x * 128;
    int tid = threadIdx.x;
    int lane = tid & 31, w = tid >> 5;
    int h = w >> 2, mq = w & 3;
    int g = lane >> 2, t = lane & 3;
    int hb = h * 64;
    int rbase = 32 * mq;
    float inv_spe = g_inv2s2_spe;

    uint32_t qh[2][4][4];
    #pragma unroll
    for (int m = 0; m < 2; m++)
        #pragma unroll
        for (int ks = 0; ks < 4; ks++)
            #pragma unroll
            for (int e = 0; e < 4; e++) {
                int row = i0 + rbase + 16 * m + g + (e & 1) * 8;
                int col = hb + 16 * ks + 2 * t + (e >> 1) * 8;
                float f0 = g_q[(size_t)(b * SEQ + row) * 128 + col];
                float f1 = g_q[(size_t)(b * SEQ + row) * 128 + col + 1];
                __half2 hi2 = __floats2half2_rn(f0, f1);
                qh[m][ks][e] = *(uint32_t*)&hi2;
            }

    float co[2][8][4] = {};
    float mA[2] = {-1e30f, -1e30f}, mB[2] = {-1e30f, -1e30f};
    float lA[2] = {0.f, 0.f},       lB[2] = {0.f, 0.f};

    int jt_begin = split * JT_PER_SPLIT;
    for (int jt = jt_begin; jt < jt_begin + JT_PER_SPLIT; jt++) {
        int j0 = jt * 64;
        #pragma unroll
        for (int fi = tid; fi < 2048; fi += 256) {
            if (fi < 1024) {
                int r = fi >> 4, c = fi & 15;
                *(uint4*)&smKH[r * 136 + c * 8] =
                    *(const uint4*)&g_kh[(size_t)(b * SEQ + j0 + r) * 128 + c * 8];
            } else {
                int v = fi - 1024, d = v >> 3, c = v & 7;
                *(uint4*)&smV[d * 136 + c * 8] =
                    *(const uint4*)&g_vh[(size_t)d * NTOK + b * SEQ + j0 + c * 8];
            }
        }
        int jx = j0 >> 6;
        #pragma unroll
        for (int ii = tid; ii < 4096; ii += 256) {
            int i = ii >> 5, c2 = (ii & 31) * 2;
            __half2 d2 = *(const __half2*)&g_dist[(size_t)(b * SEQ + i0 + i) * SEQ + j0 + c2];
            float2 df = __half22float2(d2);
            int gi = i0 + i;
            int adx = abs((gi >> 6) - jx);
            int gyi = gi & 63;
            const float* spaRow = &g_spa[adx * 64];
            float w0 = spaRow[abs(gyi - c2)] * __expf(-df.x * inv_spe);
            float w1 = spaRow[abs(gyi - (c2 + 1))] * __expf(-df.y * inv_spe);
            *(__half2*)&smWS[i * 72 + c2] = __floats2half2_rn(w0, w1);
        }
        __syncthreads();

        float cs[2][8][4] = {};
        #pragma unroll
        for (int ks = 0; ks < 4; ks++) {
            #pragma unroll
            for (int nt = 0; nt < 8; nt++) {
                int base = (8 * nt + g) * 136 + hb + 16 * ks + 2 * t;
                uint32_t kh0 = *(const uint32_t*)&smKH[base];
                uint32_t kh1 = *(const uint32_t*)&smKH[base + 8];
                mma16(cs[0][nt], qh[0][ks], kh0, kh1);
                mma16(cs[1][nt], qh[1][ks], kh0, kh1);
            }
        }

        uint32_t plo[2][8], phi[2][8];
        #pragma unroll
        for (int m = 0; m < 2; m++) {
            int r0 = rbase + 16 * m + g;
            float mloc0 = -1e30f, mloc1 = -1e30f;
            #pragma unroll
            for (int nt = 0; nt < 8; nt++) {
                int col = 8 * nt + 2 * t;
                float2 wa = __half22float2(*(const __half2*)&smWS[r0 * 72 + col]);
                float2 wb = __half22float2(*(const __half2*)&smWS[(r0 + 8) * 72 + col]);
                cs[m][nt][0] *= SCALE * wa.x; cs[m][nt][1] *= SCALE * wa.y;
                cs[m][nt][2] *= SCALE * wb.x; cs[m][nt][3] *= SCALE * wb.y;
                mloc0 = fmaxf(mloc0, fmaxf(cs[m][nt][0], cs[m][nt][1]));
                mloc1 = fmaxf(mloc1, fmaxf(cs[m][nt][2], cs[m][nt][3]));
            }
            #pragma unroll
            for (int o = 1; o <= 2; o <<= 1) {
                mloc0 = fmaxf(mloc0, __shfl_xor_sync(0xffffffffu, mloc0, o));
                mloc1 = fmaxf(mloc1, __shfl_xor_sync(0xffffffffu, mloc1, o));
            }
            float mn0 = fmaxf(mA[m], mloc0), mn1 = fmaxf(mB[m], mloc1);
            float corr0 = __expf(mA[m] - mn0), corr1 = __expf(mB[m] - mn1);
            mA[m] = mn0; mB[m] = mn1;
            float rs0 = 0.f, rs1 = 0.f;
            #pragma unroll
            for (int nt = 0; nt < 8; nt++) {
                float p0 = __expf(cs[m][nt][0] - mn0), p1 = __expf(cs[m][nt][1] - mn0);
                float p2 = __expf(cs[m][nt][2] - mn1), p3 = __expf(cs[m][nt][3] - mn1);
                rs0 += p0 + p1; rs1 += p2 + p3;
                __half2 a = __floats2half2_rn(p0, p1);
                __half2 bb = __floats2half2_rn(p2, p3);
                plo[m][nt] = *(uint32_t*)&a;
                phi[m][nt] = *(uint32_t*)&bb;
            }
            #pragma unroll
            for (int o = 1; o <= 2; o <<= 1) {
                rs0 += __shfl_xor_sync(0xffffffffu, rs0, o);
                rs1 += __shfl_xor_sync(0xffffffffu, rs1, o);
            }
            lA[m] = lA[m] * corr0 + rs0;
            lB[m] = lB[m] * corr1 + rs1;
            #pragma unroll
            for (int nt = 0; nt < 8; nt++) {
                co[m][nt][0] *= corr0; co[m][nt][1] *= corr0;
                co[m][nt][2] *= corr1; co[m][nt][3] *= corr1;
            }
        }

        #pragma unroll
        for (int ks = 0; ks < 4; ks++) {
            uint32_t pa0[4] = {plo[0][2 * ks], phi[0][2 * ks], plo[0][2 * ks + 1], phi[0][2 * ks + 1]};
            uint32_t pa1[4] = {plo[1][2 * ks], phi[1][2 * ks], plo[1][2 * ks + 1], phi[1][2 * ks + 1]};
            #pragma unroll
            for (int nt = 0; nt < 8; nt++) {
                int base = (hb + 8 * nt + g) * 136 + 16 * ks + 2 * t;
                uint32_t b0 = *(const uint32_t*)&smV[base];
                uint32_t b1 = *(const uint32_t*)&smV[base + 8];
                mma16(co[0][nt], pa0, b0, b1);
                mma16(co[1][nt], pa1, b0, b1);
            }
        }
        __syncthreads();
    }

    float* po = g_po[split];
    #pragma unroll
    for (int m = 0; m < 2; m++) {
        int row0 = b * SEQ + i0 + rbase + 16 * m + g;
        #pragma unroll
        for (int nt = 0; nt < 8; nt++) {
            int col = hb + 8 * nt + 2 * t;
            float2 o0 = {co[m][nt][0], co[m][nt][1]};
            float2 o1 = {co[m][nt][2], co[m][nt][3]};
            *(float2*)&po[(size_t)row0 * 128 + col] = o0;
            *(float2*)&po[(size_t)(row0 + 8) * 128 + col] = o1;
        }
        if (t == 0) {
            g_pml[split][row0 * 2 + h]       = make_float2(mA[m], lA[m]);
            g_pml[split][(row0 + 8) * 2 + h] = make_float2(mB[m], lB[m]);
        }
    }
}

// ---------------- merge split-KV partials ----------------
__global__ void k_merge() {
    int idx = blockIdx.x * 256 + threadIdx.x;
    int row = idx >> 7, col = idx & 127;
    int h = col >> 6;
    float2 a = g_pml[0][row * 2 + h];
    float2 bb = g_pml[1][row * 2 + h];
    float M = fmaxf(a.x, bb.x);
    float ea = __expf(a.x - M), eb = __expf(bb.x - M);
    float l = ea * a.y + eb * bb.y;
    float o = (ea * g_po[0][idx] + eb * g_po[1][idx]) / l;
    g_attn[idx] = o;
}

// ---------------- launch ----------------
extern "C" void kernel_launch(void* const* d_in, const int* in_sizes, int n_in,
                              void* d_out, int out_size) {
    const float* x      = (const float*)d_in[0];
    const float* v_qkv  = (const float*)d_in[1];
    const float* g_qkv_ = (const float*)d_in[2];
    const float* b_qkv  = (const float*)d_in[3];
    const float* v_ff1  = (const float*)d_in[4];
    const float* g_ff1  = (const float*)d_in[5];
    const float* b_ff1  = (const float*)d_in[6];
    const float* v_ff2  = (const float*)d_in[7];
    const float* g_ff2  = (const float*)d_in[8];
    const float* b_ff2  = (const float*)d_in[9];
    float* out = (float*)d_out;

    cudaFuncSetAttribute(k_gemm128, cudaFuncAttributeMaxDynamicSharedMemorySize, PG_SMEM_BYTES);
    cudaFuncSetAttribute(k_dist,    cudaFuncAttributeMaxDynamicSharedMemorySize, DIST_SMEM_BYTES);
    cudaFuncSetAttribute(k_flash,   cudaFuncAttributeMaxDynamicSharedMemorySize, FLASH_SMEM_BYTES);

    float* Wdev = nullptr;     cudaGetSymbolAddress((void**)&Wdev, g_W);
    float* attn_dev = nullptr; cudaGetSymbolAddress((void**)&attn_dev, g_attn);
    float* h1_dev = nullptr;   cudaGetSymbolAddress((void**)&h1_dev, g_q);

    // launch order: k_flash is 4th (ncu capture slot)
    k_weights_sq<<<640 + NTOK / 4, 128>>>(v_qkv, g_qkv_, v_ff1, g_ff1, v_ff2, g_ff2, x);
    k_gemm128<<<dim3(3, NTOK / 128), 256, PG_SMEM_BYTES>>>(x, Wdev, b_qkv, nullptr, 0);
    k_dist<<<dim3(32, 32, BATCH), 256, DIST_SMEM_BYTES>>>();
    k_flash<<<dim3(SEQ / 128, NSPLIT, BATCH), 256, FLASH_SMEM_BYTES>>>();
    k_merge<<<NTOK * DIM / 256, 256>>>();
    k_gemm128<<<dim3(1, NTOK / 128), 256, PG_SMEM_BYTES>>>(attn_dev, Wdev + 384 * 128, b_ff1, nullptr, 1);
    k_gemm128<<<dim3(1, NTOK / 128), 256, PG_SMEM_BYTES>>>(h1_dev, Wdev + 512 * 128, b_ff2, out, 2);
}

// round 15
// speedup vs baseline: 1.6219x; 1.0256x over previous
#include <cuda_runtime.h>
#include <cuda_fp16.h>
#include <math.h>
#include <stdint.h>

#define BATCH 2
#define SEQ   4096
#define DIM   128
#define NTOK  (BATCH * SEQ)
#define SCALE 0.125f   // 64^-0.5
#define NSPLIT 2
#define JT_PER_SPLIT (64 / NSPLIT)

// ---------------- device scratch ----------------
__device__ float  g_W[640 * 128];
__device__ float  g_q[NTOK * DIM];            // reused as h1 after flash
__device__ __half g_xh[NTOK * DIM];           // x in fp16 for dist
__device__ __half g_kh[NTOK * DIM];           // K fp16
__device__ __half g_vh[(size_t)DIM * NTOK];   // V fp16, transposed [d][tok]
__device__ float  g_sq[NTOK];
__device__ __half g_dist[(size_t)BATCH * SEQ * SEQ];
__device__ double g_sum_spe;
__device__ float  g_inv2s2_spe;
__device__ float  g_spa[64 * 64];
__device__ float  g_attn[NTOK * DIM];
__device__ float  g_po[NSPLIT][NTOK * DIM];
__device__ float2 g_pml[NSPLIT][NTOK * 2];
__device__ unsigned int g_dist_ctr = 0;

// ---------------- helpers ----------------
__device__ __forceinline__ void mma16(float* c, const uint32_t* a, uint32_t b0, uint32_t b1) {
    asm volatile("mma.sync.aligned.m16n8k16.row.col.f32.f16.f16.f32 "
                 "{%0,%1,%2,%3},{%4,%5,%6,%7},{%8,%9},{%0,%1,%2,%3};"
                 : "+f"(c[0]), "+f"(c[1]), "+f"(c[2]), "+f"(c[3])
                 : "r"(a[0]), "r"(a[1]), "r"(a[2]), "r"(a[3]), "r"(b0), "r"(b1));
}
__device__ __forceinline__ void split_h(float v, __half& hi, __half& lo) {
    hi = __float2half_rn(v);
    lo = __float2half_rn(v - __half2float(hi));
}

// ---------------- weight norm + init + ||x||^2 + x fp16 copy (fused) ----------------
__global__ void k_weights_sq(const float* __restrict__ vq, const float* __restrict__ gq,
                             const float* __restrict__ v1, const float* __restrict__ g1,
                             const float* __restrict__ v2, const float* __restrict__ g2,
                             const float* __restrict__ x) {
    int blk = blockIdx.x, t = threadIdx.x;
    if (blk >= 640) {
        int token = (blk - 640) * 4 + (t >> 5);
        int lane = t & 31;
        const float4* xp = (const float4*)(x + (size_t)token * 128);
        float4 a = xp[lane];
        __half2 h01 = __floats2half2_rn(a.x, a.y);
        __half2 h23 = __floats2half2_rn(a.z, a.w);
        uint2 u = {*(uint32_t*)&h01, *(uint32_t*)&h23};
        *(uint2*)&g_xh[(size_t)token * 128 + lane * 4] = u;
        float ss = a.x * a.x + a.y * a.y + a.z * a.z + a.w * a.w;
        #pragma unroll
        for (int o = 16; o; o >>= 1) ss += __shfl_xor_sync(0xffffffffu, ss, o);
        if (lane == 0) g_sq[token] = ss;
        return;
    }
    if (blk == 0 && t == 0) g_sum_spe = 0.0;
    int r = blk;
    const float* v; float g;
    if (r < 384)      { v = vq + r * 128;        g = gq[r]; }
    else if (r < 512) { v = v1 + (r - 384) * 128; g = g1[r - 384]; }
    else              { v = v2 + (r - 512) * 128; g = g2[r - 512]; }
    float val = v[t];
    float ss = val * val;
    #pragma unroll
    for (int o = 16; o; o >>= 1) ss += __shfl_xor_sync(0xffffffffu, ss, o);
    __shared__ float ws[4];
    if ((t & 31) == 0) ws[t >> 5] = ss;
    __syncthreads();
    float tot = ws[0] + ws[1] + ws[2] + ws[3];
    g_W[r * 128 + t] = val * (g / sqrtf(tot));
}

// ---------------- projection GEMM via fp16 MMA (A 2-term hi/lo, W hi) ----------------
#define PG_SMEM_BYTES (3 * 128 * 136 * 2)
__global__ void __launch_bounds__(256, 1) k_gemm128(const float* __restrict__ A,
                                                    const float* __restrict__ Wrows,
                                                    const float* __restrict__ bias,
                                                    float* __restrict__ out, int mode) {
    extern __shared__ __half smh[];
    __half* ah = smh;
    __half* al = smh + 128 * 136;
    __half* wh = smh + 2 * 128 * 136;
    int c0 = blockIdx.x * 128;
    int t0 = blockIdx.y * 128;
    int tid = threadIdx.x;
    for (int fi = tid; fi < 8192; fi += 256) {
        if (fi < 4096) {
            int r = fi >> 5, c4 = (fi & 31) * 4;
            float4 a = *(const float4*)&A[(size_t)(t0 + r) * 128 + c4];
            __half h0, l0, h1, l1, h2, l2, h3, l3;
            split_h(a.x, h0, l0); split_h(a.y, h1, l1);
            split_h(a.z, h2, l2); split_h(a.w, h3, l3);
            __half2 hh0 = __halves2half2(h0, h1), hh1 = __halves2half2(h2, h3);
            __half2 ll0 = __halves2half2(l0, l1), ll1 = __halves2half2(l2, l3);
            uint2 uh = {*(uint32_t*)&hh0, *(uint32_t*)&hh1};
            uint2 ul = {*(uint32_t*)&ll0, *(uint32_t*)&ll1};
            *(uint2*)&ah[r * 136 + c4] = uh;
            *(uint2*)&al[r * 136 + c4] = ul;
        } else {
            int v = fi - 4096, r = v >> 5, c4 = (v & 31) * 4;
            float4 wv = *(const float4*)&Wrows[(size_t)(c0 + r) * 128 + c4];
            __half2 hh0 = __floats2half2_rn(wv.x, wv.y);
            __half2 hh1 = __floats2half2_rn(wv.z, wv.w);
            uint2 uh = {*(uint32_t*)&hh0, *(uint32_t*)&hh1};
            *(uint2*)&wh[r * 136 + c4] = uh;
        }
    }
    __syncthreads();
    int lane = tid & 31, w = tid >> 5;
    int wr = w >> 1, wc = w & 1;
    int g = lane >> 2, t = lane & 3;
    float c[2][8][4] = {};
    #pragma unroll
    for (int ks = 0; ks < 8; ks++) {
        uint32_t Ah[2][4], Al[2][4];
        #pragma unroll
        for (int mt = 0; mt < 2; mt++)
            #pragma unroll
            for (int e = 0; e < 4; e++) {
                int idx = (32 * wr + 16 * mt + g + (e & 1) * 8) * 136
                          + 16 * ks + 2 * t + (e >> 1) * 8;
                Ah[mt][e] = *(const uint32_t*)&ah[idx];
                Al[mt][e] = *(const uint32_t*)&al[idx];
            }
        #pragma unroll
        for (int nt = 0; nt < 8; nt++) {
            int base = (64 * wc + 8 * nt + g) * 136 + 16 * ks + 2 * t;
            uint32_t b0 = *(const uint32_t*)&wh[base];
            uint32_t b1 = *(const uint32_t*)&wh[base + 8];
            mma16(c[0][nt], Ah[0], b0, b1);
            mma16(c[0][nt], Al[0], b0, b1);
            mma16(c[1][nt], Ah[1], b0, b1);
            mma16(c[1][nt], Al[1], b0, b1);
        }
    }
    #pragma unroll
    for (int mt = 0; mt < 2; mt++) {
        int irl = 32 * wr + 16 * mt + g;
        int token = t0 + irl;
        #pragma unroll
        for (int nt = 0; nt < 8; nt++) {
            int jcl = 64 * wc + 8 * nt + 2 * t;
            int col = c0 + jcl;
            float bb0 = __ldg(&bias[col]), bb1 = __ldg(&bias[col + 1]);
            float v0 = c[mt][nt][0] + bb0, v1 = c[mt][nt][1] + bb1;
            float v2 = c[mt][nt][2] + bb0, v3 = c[mt][nt][3] + bb1;
            if (mode == 0) {
                if (col < 128) {
                    *(float2*)&g_q[(size_t)token * 128 + col]       = make_float2(v0, v1);
                    *(float2*)&g_q[(size_t)(token + 8) * 128 + col] = make_float2(v2, v3);
                } else if (col < 256) {
                    int d = col - 128;
                    *(__half2*)&g_kh[(size_t)token * 128 + d]       = __floats2half2_rn(v0, v1);
                    *(__half2*)&g_kh[(size_t)(token + 8) * 128 + d] = __floats2half2_rn(v2, v3);
                } else {
                    int d = col - 256;
                    g_vh[(size_t)d * NTOK + token]           = __float2half_rn(v0);
                    g_vh[(size_t)(d + 1) * NTOK + token]     = __float2half_rn(v1);
                    g_vh[(size_t)d * NTOK + token + 8]       = __float2half_rn(v2);
                    g_vh[(size_t)(d + 1) * NTOK + token + 8] = __float2half_rn(v3);
                }
            } else if (mode == 1) {
                g_q[(size_t)token * 128 + col]           = 0.5f * v0 * (1.0f + erff(v0 * 0.70710678118654752f));
                g_q[(size_t)token * 128 + col + 1]       = 0.5f * v1 * (1.0f + erff(v1 * 0.70710678118654752f));
                g_q[(size_t)(token + 8) * 128 + col]     = 0.5f * v2 * (1.0f + erff(v2 * 0.70710678118654752f));
                g_q[(size_t)(token + 8) * 128 + col + 1] = 0.5f * v3 * (1.0f + erff(v3 * 0.70710678118654752f));
            } else {
                *(float2*)&out[(size_t)token * 128 + col]       = make_float2(v0, v1);
                *(float2*)&out[(size_t)(token + 8) * 128 + col] = make_float2(v2, v3);
            }
        }
    }
}

// ---------------- pairwise distance via fp16 MMA, symmetric blocks only ----------------
#define DIST_SMEM_BYTES (2 * 128 * 136 * 2)
__global__ void __launch_bounds__(256, 2) k_dist() {
    int bi = blockIdx.y, bj = blockIdx.x, b = blockIdx.z;
    if (bj < bi) return;
    extern __shared__ __half smh[];
    __half* xi = smh;                // [128][136]
    __half* xj = smh + 128 * 136;
    int i0 = bi * 128, j0 = bj * 128;
    int tid = threadIdx.x;
    for (int fi = tid; fi < 4096; fi += 256) {
        if (fi < 2048) {
            int r = fi >> 4, c8 = (fi & 15) * 8;
            *(uint4*)&xi[r * 136 + c8] = *(const uint4*)&g_xh[(size_t)(b * SEQ + i0 + r) * 128 + c8];
        } else {
            int v = fi - 2048, r = v >> 4, c8 = (v & 15) * 8;
            *(uint4*)&xj[r * 136 + c8] = *(const uint4*)&g_xh[(size_t)(b * SEQ + j0 + r) * 128 + c8];
        }
    }
    __syncthreads();
    int lane = tid & 31, w = tid >> 5;
    int wr = w >> 1, wc = w & 1;
    int g = lane >> 2, t = lane & 3;
    float c[2][8][4] = {};
    #pragma unroll
    for (int ks = 0; ks < 8; ks++) {
        uint32_t A[2][4];
        #pragma unroll
        for (int mt = 0; mt < 2; mt++)
            #pragma unroll
            for (int e = 0; e < 4; e++)
                A[mt][e] = *(const uint32_t*)&xi[(32 * wr + 16 * mt + g + (e & 1) * 8) * 136
                                                 + 16 * ks + 2 * t + (e >> 1) * 8];
        #pragma unroll
        for (int nt = 0; nt < 8; nt++) {
            int base = (64 * wc + 8 * nt + g) * 136 + 16 * ks + 2 * t;
            uint32_t b0 = *(const uint32_t*)&xj[base];
            uint32_t b1 = *(const uint32_t*)&xj[base + 8];
            mma16(c[0][nt], A[0], b0, b1);
            mma16(c[1][nt], A[1], b0, b1);
        }
    }
    bool diag = (bi == bj);
    __syncthreads();
    __half* sT = xi;

    float lsum = 0.f;
    #pragma unroll
    for (int mt = 0; mt < 2; mt++) {
        int irl = 32 * wr + 16 * mt + g;
        int ir0 = i0 + irl;
        float sqi0 = __ldg(&g_sq[b * SEQ + ir0]);
        float sqi1 = __ldg(&g_sq[b * SEQ + ir0 + 8]);
        #pragma unroll
        for (int nt = 0; nt < 8; nt++) {
            int jcl = 64 * wc + 8 * nt + 2 * t;
            int jc = j0 + jcl;
            float sj0 = __ldg(&g_sq[b * SEQ + jc]);
            float sj1 = __ldg(&g_sq[b * SEQ + jc + 1]);
            float d00 = sqrtf(fmaxf(sqi0 + sj0 - 2.f * c[mt][nt][0], 0.f));
            float d01 = sqrtf(fmaxf(sqi0 + sj1 - 2.f * c[mt][nt][1], 0.f));
            float d10 = sqrtf(fmaxf(sqi1 + sj0 - 2.f * c[mt][nt][2], 0.f));
            float d11 = sqrtf(fmaxf(sqi1 + sj1 - 2.f * c[mt][nt][3], 0.f));
            lsum += d00 + d01 + d10 + d11;
            __half2 p0 = __floats2half2_rn(d00, d01);
            __half2 p1 = __floats2half2_rn(d10, d11);
            *(__half2*)&g_dist[(size_t)(b * SEQ + ir0) * SEQ + jc]     = p0;
            *(__half2*)&g_dist[(size_t)(b * SEQ + ir0 + 8) * SEQ + jc] = p1;
            if (!diag) {
                sT[jcl * 136 + irl]           = __low2half(p0);
                sT[(jcl + 1) * 136 + irl]     = __high2half(p0);
                sT[jcl * 136 + irl + 8]       = __low2half(p1);
                sT[(jcl + 1) * 136 + irl + 8] = __high2half(p1);
            }
        }
    }
    if (!diag) {
        __syncthreads();
        for (int fi = tid; fi < 2048; fi += 256) {
            int jl = fi >> 4, c8 = (fi & 15) * 8;
            *(uint4*)&g_dist[(size_t)(b * SEQ + j0 + jl) * SEQ + i0 + c8] =
                *(const uint4*)&sT[jl * 136 + c8];
        }
    }
    #pragma unroll
    for (int o = 16; o; o >>= 1) lsum += __shfl_xor_sync(0xffffffffu, lsum, o);
    __shared__ float rsum[8];
    if (lane == 0) rsum[w] = lsum;
    __syncthreads();
    __shared__ bool is_last;
    if (tid == 0) {
        float tot = 0.f;
        #pragma unroll
        for (int i = 0; i < 8; i++) tot += rsum[i];
        atomicAdd(&g_sum_spe, (double)(diag ? tot : 2.f * tot));
        __threadfence();
        unsigned int nwork = (32 * 33 / 2) * gridDim.z;
        unsigned int cdone = atomicAdd(&g_dist_ctr, 1u);
        is_last = (cdone == nwork - 1);
    }
    __syncthreads();
    if (!is_last) return;

    int t2 = tid;
    __shared__ double red[256];
    double local = 0.0;
    for (int idx = t2; idx < 64 * 64; idx += 256) {
        int adx = idx >> 6, ady = idx & 63;
        double cx = adx ? 2.0 * (64 - adx) : 64.0;
        double cy = ady ? 2.0 * (64 - ady) : 64.0;
        local += cx * cy * sqrt((double)(adx * adx + ady * ady));
    }
    red[t2] = local; __syncthreads();
    for (int s = 128; s; s >>= 1) { if (t2 < s) red[t2] += red[t2 + s]; __syncthreads(); }
    __shared__ float inv_spa;
    if (t2 == 0) {
        double sig_spa = red[0] / ((double)SEQ * (double)SEQ);
        inv_spa = (float)(1.0 / (2.0 * sig_spa * sig_spa));
        double sig_spe = g_sum_spe / ((double)BATCH * (double)SEQ * (double)SEQ);
        g_inv2s2_spe = (float)(1.0 / (2.0 * sig_spe * sig_spe));
        g_dist_ctr = 0;
    }
    __syncthreads();
    float iv = inv_spa;
    for (int idx = t2; idx < 64 * 64; idx += 256) {
        int adx = idx >> 6, ady = idx & 63;
        g_spa[idx] = expf(-sqrtf((float)(adx * adx + ady * ady)) * iv);
    }
}

// ---------------- flash attention: 512 threads, 16 warps (16 rows x 1 head each) ----------------
#define FL_V_HOFF  8704
#define FL_WS_HOFF 26112
#define FLASH_SMEM_BYTES ((FL_WS_HOFF + 128 * 72) * 2)
__global__ void __launch_bounds__(512, 1) k_flash() {
    extern __shared__ __half smh[];
    __half* smKH = smh;
    __half* smV  = smh + FL_V_HOFF;
    __half* smWS = smh + FL_WS_HOFF;
    int b     = blockIdx.z;
    int split = blockIdx.y;
    int i0 = blockIdx.x * 128;
    int tid = threadIdx.x;
    int lane = tid & 31, w = tid >> 5;
    int h = w >> 3, mq = w & 7;          // head, 16-row strip
    int g = lane >> 2, t = lane & 3;
    int hb = h * 64;
    int rbase = 16 * mq;
    float inv_spe = g_inv2s2_spe;

    // Q fragments fp16-hi: one 16-row strip, 4 k-steps
    uint32_t qh[4][4];
    #pragma unroll
    for (int ks = 0; ks < 4; ks++)
        #pragma unroll
        for (int e = 0; e < 4; e++) {
            int row = i0 + rbase + g + (e & 1) * 8;
            int col = hb + 16 * ks + 2 * t + (e >> 1) * 8;
            float f0 = g_q[(size_t)(b * SEQ + row) * 128 + col];
            float f1 = g_q[(size_t)(b * SEQ + row) * 128 + col + 1];
            __half2 hi2 = __floats2half2_rn(f0, f1);
            qh[ks][e] = *(uint32_t*)&hi2;
        }

    float co[8][4] = {};
    float mA = -1e30f, mB = -1e30f, lA = 0.f, lB = 0.f;

    int jt_begin = split * JT_PER_SPLIT;
    for (int jt = jt_begin; jt < jt_begin + JT_PER_SPLIT; jt++) {
        int j0 = jt * 64;
        #pragma unroll
        for (int fi = tid; fi < 2048; fi += 512) {
            if (fi < 1024) {
                int r = fi >> 4, c = fi & 15;
                *(uint4*)&smKH[r * 136 + c * 8] =
                    *(const uint4*)&g_kh[(size_t)(b * SEQ + j0 + r) * 128 + c * 8];
            } else {
                int v = fi - 1024, d = v >> 3, c = v & 7;
                *(uint4*)&smV[d * 136 + c * 8] =
                    *(const uint4*)&g_vh[(size_t)d * NTOK + b * SEQ + j0 + c * 8];
            }
        }
        int jx = j0 >> 6;
        #pragma unroll
        for (int ii = tid; ii < 4096; ii += 512) {
            int i = ii >> 5, c2 = (ii & 31) * 2;
            __half2 d2 = *(const __half2*)&g_dist[(size_t)(b * SEQ + i0 + i) * SEQ + j0 + c2];
            float2 df = __half22float2(d2);
            int gi = i0 + i;
            int adx = abs((gi >> 6) - jx);
            int gyi = gi & 63;
            const float* spaRow = &g_spa[adx * 64];
            float w0 = spaRow[abs(gyi - c2)] * __expf(-df.x * inv_spe);
            float w1 = spaRow[abs(gyi - (c2 + 1))] * __expf(-df.y * inv_spe);
            *(__half2*)&smWS[i * 72 + c2] = __floats2half2_rn(w0, w1);
        }
        __syncthreads();

        // ---- QK^T: 1-term fp16 ----
        float cs[8][4] = {};
        #pragma unroll
        for (int ks = 0; ks < 4; ks++) {
            #pragma unroll
            for (int nt = 0; nt < 8; nt++) {
                int base = (8 * nt + g) * 136 + hb + 16 * ks + 2 * t;
                uint32_t kh0 = *(const uint32_t*)&smKH[base];
                uint32_t kh1 = *(const uint32_t*)&smKH[base + 8];
                mma16(cs[nt], qh[ks], kh0, kh1);
            }
        }

        // ---- mask + online softmax ----
        int r0 = rbase + g;
        float mloc0 = -1e30f, mloc1 = -1e30f;
        #pragma unroll
        for (int nt = 0; nt < 8; nt++) {
            int col = 8 * nt + 2 * t;
            float2 wa = __half22float2(*(const __half2*)&smWS[r0 * 72 + col]);
            float2 wb = __half22float2(*(const __half2*)&smWS[(r0 + 8) * 72 + col]);
            cs[nt][0] *= SCALE * wa.x; cs[nt][1] *= SCALE * wa.y;
            cs[nt][2] *= SCALE * wb.x; cs[nt][3] *= SCALE * wb.y;
            mloc0 = fmaxf(mloc0, fmaxf(cs[nt][0], cs[nt][1]));
            mloc1 = fmaxf(mloc1, fmaxf(cs[nt][2], cs[nt][3]));
        }
        #pragma unroll
        for (int o = 1; o <= 2; o <<= 1) {
            mloc0 = fmaxf(mloc0, __shfl_xor_sync(0xffffffffu, mloc0, o));
            mloc1 = fmaxf(mloc1, __shfl_xor_sync(0xffffffffu, mloc1, o));
        }
        float mn0 = fmaxf(mA, mloc0), mn1 = fmaxf(mB, mloc1);
        float corr0 = __expf(mA - mn0), corr1 = __expf(mB - mn1);
        mA = mn0; mB = mn1;
        float rs0 = 0.f, rs1 = 0.f;
        uint32_t plo[8], phi[8];
        #pragma unroll
        for (int nt = 0; nt < 8; nt++) {
            float p0 = __expf(cs[nt][0] - mn0), p1 = __expf(cs[nt][1] - mn0);
            float p2 = __expf(cs[nt][2] - mn1), p3 = __expf(cs[nt][3] - mn1);
            rs0 += p0 + p1; rs1 += p2 + p3;
            __half2 a = __floats2half2_rn(p0, p1);
            __half2 bb = __floats2half2_rn(p2, p3);
            plo[nt] = *(uint32_t*)&a;
            phi[nt] = *(uint32_t*)&bb;
        }
        #pragma unroll
        for (int o = 1; o <= 2; o <<= 1) {
            rs0 += __shfl_xor_sync(0xffffffffu, rs0, o);
            rs1 += __shfl_xor_sync(0xffffffffu, rs1, o);
        }
        lA = lA * corr0 + rs0;
        lB = lB * corr1 + rs1;
        #pragma unroll
        for (int nt = 0; nt < 8; nt++) {
            co[nt][0] *= corr0; co[nt][1] *= corr0;
            co[nt][2] *= corr1; co[nt][3] *= corr1;
        }

        // ---- PV: plain fp16 from registers ----
        #pragma unroll
        for (int ks = 0; ks < 4; ks++) {
            uint32_t pa[4] = {plo[2 * ks], phi[2 * ks], plo[2 * ks + 1], phi[2 * ks + 1]};
            #pragma unroll
            for (int nt = 0; nt < 8; nt++) {
                int base = (hb + 8 * nt + g) * 136 + 16 * ks + 2 * t;
                uint32_t b0 = *(const uint32_t*)&smV[base];
                uint32_t b1 = *(const uint32_t*)&smV[base + 8];
                mma16(co[nt], pa, b0, b1);
            }
        }
        __syncthreads();
    }

    // ---- epilogue: unnormalized partials + (m, l) ----
    float* po = g_po[split];
    int row0 = b * SEQ + i0 + rbase + g;
    #pragma unroll
    for (int nt = 0; nt < 8; nt++) {
        int col = hb + 8 * nt + 2 * t;
        float2 o0 = {co[nt][0], co[nt][1]};
        float2 o1 = {co[nt][2], co[nt][3]};
        *(float2*)&po[(size_t)row0 * 128 + col] = o0;
        *(float2*)&po[(size_t)(row0 + 8) * 128 + col] = o1;
    }
    if (t == 0) {
        g_pml[split][row0 * 2 + h]       = make_float2(mA, lA);
        g_pml[split][(row0 + 8) * 2 + h] = make_float2(mB, lB);
    }
}

// ---------------- merge split-KV partials ----------------
__global__ void k_merge() {
    int idx = blockIdx.x * 256 + threadIdx.x;
    int row = idx >> 7, col = idx & 127;
    int h = col >> 6;
    float2 a = g_pml[0][row * 2 + h];
    float2 bb = g_pml[1][row * 2 + h];
    float M = fmaxf(a.x, bb.x);
    float ea = __expf(a.x - M), eb = __expf(bb.x - M);
    float l = ea * a.y + eb * bb.y;
    float o = (ea * g_po[0][idx] + eb * g_po[1][idx]) / l;
    g_attn[idx] = o;
}

// ---------------- launch ----------------
extern "C" void kernel_launch(void* const* d_in, const int* in_sizes, int n_in,
                              void* d_out, int out_size) {
    const float* x      = (const float*)d_in[0];
    const float* v_qkv  = (const float*)d_in[1];
    const float* g_qkv_ = (const float*)d_in[2];
    const float* b_qkv  = (const float*)d_in[3];
    const float* v_ff1  = (const float*)d_in[4];
    const float* g_ff1  = (const float*)d_in[5];
    const float* b_ff1  = (const float*)d_in[6];
    const float* v_ff2  = (const float*)d_in[7];
    const float* g_ff2  = (const float*)d_in[8];
    const float* b_ff2  = (const float*)d_in[9];
    float* out = (float*)d_out;

    cudaFuncSetAttribute(k_gemm128, cudaFuncAttributeMaxDynamicSharedMemorySize, PG_SMEM_BYTES);
    cudaFuncSetAttribute(k_dist,    cudaFuncAttributeMaxDynamicSharedMemorySize, DIST_SMEM_BYTES);
    cudaFuncSetAttribute(k_flash,   cudaFuncAttributeMaxDynamicSharedMemorySize, FLASH_SMEM_BYTES);

    float* Wdev = nullptr;     cudaGetSymbolAddress((void**)&Wdev, g_W);
    float* attn_dev = nullptr; cudaGetSymbolAddress((void**)&attn_dev, g_attn);
    float* h1_dev = nullptr;   cudaGetSymbolAddress((void**)&h1_dev, g_q);

    // launch order: k_flash is 4th (ncu capture slot)
    k_weights_sq<<<640 + NTOK / 4, 128>>>(v_qkv, g_qkv_, v_ff1, g_ff1, v_ff2, g_ff2, x);
    k_gemm128<<<dim3(3, NTOK / 128), 256, PG_SMEM_BYTES>>>(x, Wdev, b_qkv, nullptr, 0);
    k_dist<<<dim3(32, 32, BATCH), 256, DIST_SMEM_BYTES>>>();
    k_flash<<<dim3(SEQ / 128, NSPLIT, BATCH), 512, FLASH_SMEM_BYTES>>>();
    k_merge<<<NTOK * DIM / 256, 256>>>();
    k_gemm128<<<dim3(1, NTOK / 128), 256, PG_SMEM_BYTES>>>(attn_dev, Wdev + 384 * 128, b_ff1, nullptr, 1);
    k_gemm128<<<dim3(1, NTOK / 128), 256, PG_SMEM_BYTES>>>(h1_dev, Wdev + 512 * 128, b_ff2, out, 2);
}

// round 16
// speedup vs baseline: 1.6653x; 1.0268x over previous
#include <cuda_runtime.h>
#include <cuda_fp16.h>
#include <math.h>
#include <stdint.h>

#define BATCH 2
#define SEQ   4096
#define DIM   128
#define NTOK  (BATCH * SEQ)
#define SCALE 0.125f   // 64^-0.5
#define NSPLIT 2
#define JT_PER_SPLIT (64 / NSPLIT)

// ---------------- device scratch ----------------
__device__ float  g_W[640 * 128];
__device__ float  g_q[NTOK * DIM];            // reused as h1 after flash
__device__ __half g_xh[NTOK * DIM];           // x in fp16 for dist
__device__ __half g_kh[NTOK * DIM];           // K fp16
__device__ __half g_vh[(size_t)DIM * NTOK];   // V fp16, transposed [d][tok]
__device__ float  g_sq[NTOK];
__device__ __half g_dist[(size_t)BATCH * SEQ * SEQ];
__device__ double g_sum_spe;
__device__ float  g_inv2s2_spe;
__device__ float  g_spa[64 * 64];
__device__ float  g_attn[NTOK * DIM];
__device__ float  g_po[NSPLIT][NTOK * DIM];
__device__ float2 g_pml[NSPLIT][NTOK * 2];
__device__ unsigned int g_dist_ctr = 0;

// ---------------- helpers ----------------
__device__ __forceinline__ void mma16(float* c, const uint32_t* a, uint32_t b0, uint32_t b1) {
    asm volatile("mma.sync.aligned.m16n8k16.row.col.f32.f16.f16.f32 "
                 "{%0,%1,%2,%3},{%4,%5,%6,%7},{%8,%9},{%0,%1,%2,%3};"
                 : "+f"(c[0]), "+f"(c[1]), "+f"(c[2]), "+f"(c[3])
                 : "r"(a[0]), "r"(a[1]), "r"(a[2]), "r"(a[3]), "r"(b0), "r"(b1));
}
__device__ __forceinline__ void split_h(float v, __half& hi, __half& lo) {
    hi = __float2half_rn(v);
    lo = __float2half_rn(v - __half2float(hi));
}

// ---------------- weight norm + init + ||x||^2 + x fp16 copy (fused) ----------------
__global__ void k_weights_sq(const float* __restrict__ vq, const float* __restrict__ gq,
                             const float* __restrict__ v1, const float* __restrict__ g1,
                             const float* __restrict__ v2, const float* __restrict__ g2,
                             const float* __restrict__ x) {
    int blk = blockIdx.x, t = threadIdx.x;
    if (blk >= 640) {
        int token = (blk - 640) * 4 + (t >> 5);
        int lane = t & 31;
        const float4* xp = (const float4*)(x + (size_t)token * 128);
        float4 a = xp[lane];
        __half2 h01 = __floats2half2_rn(a.x, a.y);
        __half2 h23 = __floats2half2_rn(a.z, a.w);
        uint2 u = {*(uint32_t*)&h01, *(uint32_t*)&h23};
        *(uint2*)&g_xh[(size_t)token * 128 + lane * 4] = u;
        float ss = a.x * a.x + a.y * a.y + a.z * a.z + a.w * a.w;
        #pragma unroll
        for (int o = 16; o; o >>= 1) ss += __shfl_xor_sync(0xffffffffu, ss, o);
        if (lane == 0) g_sq[token] = ss;
        return;
    }
    if (blk == 0 && t == 0) g_sum_spe = 0.0;
    int r = blk;
    const float* v; float g;
    if (r < 384)      { v = vq + r * 128;        g = gq[r]; }
    else if (r < 512) { v = v1 + (r - 384) * 128; g = g1[r - 384]; }
    else              { v = v2 + (r - 512) * 128; g = g2[r - 512]; }
    float val = v[t];
    float ss = val * val;
    #pragma unroll
    for (int o = 16; o; o >>= 1) ss += __shfl_xor_sync(0xffffffffu, ss, o);
    __shared__ float ws[4];
    if ((t & 31) == 0) ws[t >> 5] = ss;
    __syncthreads();
    float tot = ws[0] + ws[1] + ws[2] + ws[3];
    g_W[r * 128 + t] = val * (g / sqrtf(tot));
}

// ---------------- projection GEMM via fp16 MMA (A 2-term hi/lo, W hi) ----------------
#define PG_SMEM_BYTES (3 * 128 * 136 * 2)
__global__ void __launch_bounds__(256, 1) k_gemm128(const float* __restrict__ A,
                                                    const float* __restrict__ Wrows,
                                                    const float* __restrict__ bias,
                                                    float* __restrict__ out, int mode) {
    extern __shared__ __half smh[];
    __half* ah = smh;
    __half* al = smh + 128 * 136;
    __half* wh = smh + 2 * 128 * 136;
    int c0 = blockIdx.x * 128;
    int t0 = blockIdx.y * 128;
    int tid = threadIdx.x;
    for (int fi = tid; fi < 8192; fi += 256) {
        if (fi < 4096) {
            int r = fi >> 5, c4 = (fi & 31) * 4;
            float4 a = *(const float4*)&A[(size_t)(t0 + r) * 128 + c4];
            __half h0, l0, h1, l1, h2, l2, h3, l3;
            split_h(a.x, h0, l0); split_h(a.y, h1, l1);
            split_h(a.z, h2, l2); split_h(a.w, h3, l3);
            __half2 hh0 = __halves2half2(h0, h1), hh1 = __halves2half2(h2, h3);
            __half2 ll0 = __halves2half2(l0, l1), ll1 = __halves2half2(l2, l3);
            uint2 uh = {*(uint32_t*)&hh0, *(uint32_t*)&hh1};
            uint2 ul = {*(uint32_t*)&ll0, *(uint32_t*)&ll1};
            *(uint2*)&ah[r * 136 + c4] = uh;
            *(uint2*)&al[r * 136 + c4] = ul;
        } else {
            int v = fi - 4096, r = v >> 5, c4 = (v & 31) * 4;
            float4 wv = *(const float4*)&Wrows[(size_t)(c0 + r) * 128 + c4];
            __half2 hh0 = __floats2half2_rn(wv.x, wv.y);
            __half2 hh1 = __floats2half2_rn(wv.z, wv.w);
            uint2 uh = {*(uint32_t*)&hh0, *(uint32_t*)&hh1};
            *(uint2*)&wh[r * 136 + c4] = uh;
        }
    }
    __syncthreads();
    int lane = tid & 31, w = tid >> 5;
    int wr = w >> 1, wc = w & 1;
    int g = lane >> 2, t = lane & 3;
    float c[2][8][4] = {};
    #pragma unroll
    for (int ks = 0; ks < 8; ks++) {
        uint32_t Ah[2][4], Al[2][4];
        #pragma unroll
        for (int mt = 0; mt < 2; mt++)
            #pragma unroll
            for (int e = 0; e < 4; e++) {
                int idx = (32 * wr + 16 * mt + g + (e & 1) * 8) * 136
                          + 16 * ks + 2 * t + (e >> 1) * 8;
                Ah[mt][e] = *(const uint32_t*)&ah[idx];
                Al[mt][e] = *(const uint32_t*)&al[idx];
            }
        #pragma unroll
        for (int nt = 0; nt < 8; nt++) {
            int base = (64 * wc + 8 * nt + g) * 136 + 16 * ks + 2 * t;
            uint32_t b0 = *(const uint32_t*)&wh[base];
            uint32_t b1 = *(const uint32_t*)&wh[base + 8];
            mma16(c[0][nt], Ah[0], b0, b1);
            mma16(c[0][nt], Al[0], b0, b1);
            mma16(c[1][nt], Ah[1], b0, b1);
            mma16(c[1][nt], Al[1], b0, b1);
        }
    }
    #pragma unroll
    for (int mt = 0; mt < 2; mt++) {
        int irl = 32 * wr + 16 * mt + g;
        int token = t0 + irl;
        #pragma unroll
        for (int nt = 0; nt < 8; nt++) {
            int jcl = 64 * wc + 8 * nt + 2 * t;
            int col = c0 + jcl;
            float bb0 = __ldg(&bias[col]), bb1 = __ldg(&bias[col + 1]);
            float v0 = c[mt][nt][0] + bb0, v1 = c[mt][nt][1] + bb1;
            float v2 = c[mt][nt][2] + bb0, v3 = c[mt][nt][3] + bb1;
            if (mode == 0) {
                if (col < 128) {
                    *(float2*)&g_q[(size_t)token * 128 + col]       = make_float2(v0, v1);
                    *(float2*)&g_q[(size_t)(token + 8) * 128 + col] = make_float2(v2, v3);
                } else if (col < 256) {
                    int d = col - 128;
                    *(__half2*)&g_kh[(size_t)token * 128 + d]       = __floats2half2_rn(v0, v1);
                    *(__half2*)&g_kh[(size_t)(token + 8) * 128 + d] = __floats2half2_rn(v2, v3);
                } else {
                    int d = col - 256;
                    g_vh[(size_t)d * NTOK + token]           = __float2half_rn(v0);
                    g_vh[(size_t)(d + 1) * NTOK + token]     = __float2half_rn(v1);
                    g_vh[(size_t)d * NTOK + token + 8]       = __float2half_rn(v2);
                    g_vh[(size_t)(d + 1) * NTOK + token + 8] = __float2half_rn(v3);
                }
            } else if (mode == 1) {
                g_q[(size_t)token * 128 + col]           = 0.5f * v0 * (1.0f + erff(v0 * 0.70710678118654752f));
                g_q[(size_t)token * 128 + col + 1]       = 0.5f * v1 * (1.0f + erff(v1 * 0.70710678118654752f));
                g_q[(size_t)(token + 8) * 128 + col]     = 0.5f * v2 * (1.0f + erff(v2 * 0.70710678118654752f));
                g_q[(size_t)(token + 8) * 128 + col + 1] = 0.5f * v3 * (1.0f + erff(v3 * 0.70710678118654752f));
            } else {
                *(float2*)&out[(size_t)token * 128 + col]       = make_float2(v0, v1);
                *(float2*)&out[(size_t)(token + 8) * 128 + col] = make_float2(v2, v3);
            }
        }
    }
}

// ---------------- pairwise distance via fp16 MMA, symmetric blocks only ----------------
#define DIST_SMEM_BYTES (2 * 128 * 136 * 2)
__global__ void __launch_bounds__(256, 2) k_dist() {
    int bi = blockIdx.y, bj = blockIdx.x, b = blockIdx.z;
    if (bj < bi) return;
    extern __shared__ __half smh[];
    __half* xi = smh;                // [128][136]
    __half* xj = smh + 128 * 136;
    int i0 = bi * 128, j0 = bj * 128;
    int tid = threadIdx.x;
    for (int fi = tid; fi < 4096; fi += 256) {
        if (fi < 2048) {
            int r = fi >> 4, c8 = (fi & 15) * 8;
            *(uint4*)&xi[r * 136 + c8] = *(const uint4*)&g_xh[(size_t)(b * SEQ + i0 + r) * 128 + c8];
        } else {
            int v = fi - 2048, r = v >> 4, c8 = (v & 15) * 8;
            *(uint4*)&xj[r * 136 + c8] = *(const uint4*)&g_xh[(size_t)(b * SEQ + j0 + r) * 128 + c8];
        }
    }
    __syncthreads();
    int lane = tid & 31, w = tid >> 5;
    int wr = w >> 1, wc = w & 1;
    int g = lane >> 2, t = lane & 3;
    float c[2][8][4] = {};
    #pragma unroll
    for (int ks = 0; ks < 8; ks++) {
        uint32_t A[2][4];
        #pragma unroll
        for (int mt = 0; mt < 2; mt++)
            #pragma unroll
            for (int e = 0; e < 4; e++)
                A[mt][e] = *(const uint32_t*)&xi[(32 * wr + 16 * mt + g + (e & 1) * 8) * 136
                                                 + 16 * ks + 2 * t + (e >> 1) * 8];
        #pragma unroll
        for (int nt = 0; nt < 8; nt++) {
            int base = (64 * wc + 8 * nt + g) * 136 + 16 * ks + 2 * t;
            uint32_t b0 = *(const uint32_t*)&xj[base];
            uint32_t b1 = *(const uint32_t*)&xj[base + 8];
            mma16(c[0][nt], A[0], b0, b1);
            mma16(c[1][nt], A[1], b0, b1);
        }
    }
    bool diag = (bi == bj);
    __syncthreads();
    __half* sT = xi;

    float lsum = 0.f;
    #pragma unroll
    for (int mt = 0; mt < 2; mt++) {
        int irl = 32 * wr + 16 * mt + g;
        int ir0 = i0 + irl;
        float sqi0 = __ldg(&g_sq[b * SEQ + ir0]);
        float sqi1 = __ldg(&g_sq[b * SEQ + ir0 + 8]);
        #pragma unroll
        for (int nt = 0; nt < 8; nt++) {
            int jcl = 64 * wc + 8 * nt + 2 * t;
            int jc = j0 + jcl;
            float sj0 = __ldg(&g_sq[b * SEQ + jc]);
            float sj1 = __ldg(&g_sq[b * SEQ + jc + 1]);
            float d00 = sqrtf(fmaxf(sqi0 + sj0 - 2.f * c[mt][nt][0], 0.f));
            float d01 = sqrtf(fmaxf(sqi0 + sj1 - 2.f * c[mt][nt][1], 0.f));
            float d10 = sqrtf(fmaxf(sqi1 + sj0 - 2.f * c[mt][nt][2], 0.f));
            float d11 = sqrtf(fmaxf(sqi1 + sj1 - 2.f * c[mt][nt][3], 0.f));
            lsum += d00 + d01 + d10 + d11;
            __half2 p0 = __floats2half2_rn(d00, d01);
            __half2 p1 = __floats2half2_rn(d10, d11);
            *(__half2*)&g_dist[(size_t)(b * SEQ + ir0) * SEQ + jc]     = p0;
            *(__half2*)&g_dist[(size_t)(b * SEQ + ir0 + 8) * SEQ + jc] = p1;
            if (!diag) {
                sT[jcl * 136 + irl]           = __low2half(p0);
                sT[(jcl + 1) * 136 + irl]     = __high2half(p0);
                sT[jcl * 136 + irl + 8]       = __low2half(p1);
                sT[(jcl + 1) * 136 + irl + 8] = __high2half(p1);
            }
        }
    }
    if (!diag) {
        __syncthreads();
        for (int fi = tid; fi < 2048; fi += 256) {
            int jl = fi >> 4, c8 = (fi & 15) * 8;
            *(uint4*)&g_dist[(size_t)(b * SEQ + j0 + jl) * SEQ + i0 + c8] =
                *(const uint4*)&sT[jl * 136 + c8];
        }
    }
    #pragma unroll
    for (int o = 16; o; o >>= 1) lsum += __shfl_xor_sync(0xffffffffu, lsum, o);
    __shared__ float rsum[8];
    if (lane == 0) rsum[w] = lsum;
    __syncthreads();
    __shared__ bool is_last;
    if (tid == 0) {
        float tot = 0.f;
        #pragma unroll
        for (int i = 0; i < 8; i++) tot += rsum[i];
        atomicAdd(&g_sum_spe, (double)(diag ? tot : 2.f * tot));
        __threadfence();
        unsigned int nwork = (32 * 33 / 2) * gridDim.z;
        unsigned int cdone = atomicAdd(&g_dist_ctr, 1u);
        is_last = (cdone == nwork - 1);
    }
    __syncthreads();
    if (!is_last) return;

    int t2 = tid;
    __shared__ double red[256];
    double local = 0.0;
    for (int idx = t2; idx < 64 * 64; idx += 256) {
        int adx = idx >> 6, ady = idx & 63;
        double cx = adx ? 2.0 * (64 - adx) : 64.0;
        double cy = ady ? 2.0 * (64 - ady) : 64.0;
        local += cx * cy * sqrt((double)(adx * adx + ady * ady));
    }
    red[t2] = local; __syncthreads();
    for (int s = 128; s; s >>= 1) { if (t2 < s) red[t2] += red[t2 + s]; __syncthreads(); }
    __shared__ float inv_spa;
    if (t2 == 0) {
        double sig_spa = red[0] / ((double)SEQ * (double)SEQ);
        inv_spa = (float)(1.0 / (2.0 * sig_spa * sig_spa));
        double sig_spe = g_sum_spe / ((double)BATCH * (double)SEQ * (double)SEQ);
        g_inv2s2_spe = (float)(1.0 / (2.0 * sig_spe * sig_spe));
        g_dist_ctr = 0;
    }
    __syncthreads();
    float iv = inv_spa;
    for (int idx = t2; idx < 64 * 64; idx += 256) {
        int adx = idx >> 6, ady = idx & 63;
        g_spa[idx] = expf(-sqrtf((float)(adx * adx + ady * ady)) * iv);
    }
}

// ---------------- flash attention: 512 threads, 16 warps, double-buffered KV+WS ----------------
// per-buffer halves: KH[64][136]=8704, V[128][136]=17408, WS[128][72]=9216 -> 35328 halves
#define FLB_V   8704
#define FLB_WS  26112
#define FLB_SZ  35328
#define FLASH_SMEM_BYTES (2 * FLB_SZ * 2)   // 141312
__global__ void __launch_bounds__(512, 1) k_flash() {
    extern __shared__ __half smh[];
    int b     = blockIdx.z;
    int split = blockIdx.y;
    int i0 = blockIdx.x * 128;
    int tid = threadIdx.x;
    int lane = tid & 31, w = tid >> 5;
    int h = w >> 3, mq = w & 7;          // head, 16-row strip
    int g = lane >> 2, t = lane & 3;
    int hb = h * 64;
    int rbase = 16 * mq;
    float inv_spe = g_inv2s2_spe;

    auto fill = [&](int pbuf, int j0) {
        __half* KH = smh + pbuf * FLB_SZ;
        __half* VV = KH + FLB_V;
        __half* WS = KH + FLB_WS;
        #pragma unroll
        for (int fi = tid; fi < 2048; fi += 512) {
            if (fi < 1024) {
                int r = fi >> 4, c = fi & 15;
                *(uint4*)&KH[r * 136 + c * 8] =
                    *(const uint4*)&g_kh[(size_t)(b * SEQ + j0 + r) * 128 + c * 8];
            } else {
                int v = fi - 1024, d = v >> 3, c = v & 7;
                *(uint4*)&VV[d * 136 + c * 8] =
                    *(const uint4*)&g_vh[(size_t)d * NTOK + b * SEQ + j0 + c * 8];
            }
        }
        int jx = j0 >> 6;
        #pragma unroll
        for (int ii = tid; ii < 4096; ii += 512) {
            int i = ii >> 5, c2 = (ii & 31) * 2;
            __half2 d2 = *(const __half2*)&g_dist[(size_t)(b * SEQ + i0 + i) * SEQ + j0 + c2];
            float2 df = __half22float2(d2);
            int gi = i0 + i;
            int adx = abs((gi >> 6) - jx);
            int gyi = gi & 63;
            const float* spaRow = &g_spa[adx * 64];
            float w0 = spaRow[abs(gyi - c2)] * __expf(-df.x * inv_spe);
            float w1 = spaRow[abs(gyi - (c2 + 1))] * __expf(-df.y * inv_spe);
            *(__half2*)&WS[i * 72 + c2] = __floats2half2_rn(w0, w1);
        }
    };

    // Q fragments fp16-hi: one 16-row strip, 4 k-steps
    uint32_t qh[4][4];
    #pragma unroll
    for (int ks = 0; ks < 4; ks++)
        #pragma unroll
        for (int e = 0; e < 4; e++) {
            int row = i0 + rbase + g + (e & 1) * 8;
            int col = hb + 16 * ks + 2 * t + (e >> 1) * 8;
            float f0 = g_q[(size_t)(b * SEQ + row) * 128 + col];
            float f1 = g_q[(size_t)(b * SEQ + row) * 128 + col + 1];
            __half2 hi2 = __floats2half2_rn(f0, f1);
            qh[ks][e] = *(uint32_t*)&hi2;
        }

    float co[8][4] = {};
    float mA = -1e30f, mB = -1e30f, lA = 0.f, lB = 0.f;

    int jt_begin = split * JT_PER_SPLIT;
    fill(0, jt_begin * 64);
    __syncthreads();

    for (int jt = jt_begin; jt < jt_begin + JT_PER_SPLIT; jt++) {
        int p = (jt - jt_begin) & 1;
        if (jt + 1 < jt_begin + JT_PER_SPLIT)
            fill(1 - p, (jt + 1) * 64);       // prefetch next tile
        const __half* smKH = smh + p * FLB_SZ;
        const __half* smV  = smKH + FLB_V;
        const __half* smWS = smKH + FLB_WS;

        // ---- QK^T: 1-term fp16 ----
        float cs[8][4] = {};
        #pragma unroll
        for (int ks = 0; ks < 4; ks++) {
            #pragma unroll
            for (int nt = 0; nt < 8; nt++) {
                int base = (8 * nt + g) * 136 + hb + 16 * ks + 2 * t;
                uint32_t kh0 = *(const uint32_t*)&smKH[base];
                uint32_t kh1 = *(const uint32_t*)&smKH[base + 8];
                mma16(cs[nt], qh[ks], kh0, kh1);
            }
        }

        // ---- mask + online softmax ----
        int r0 = rbase + g;
        float mloc0 = -1e30f, mloc1 = -1e30f;
        #pragma unroll
        for (int nt = 0; nt < 8; nt++) {
            int col = 8 * nt + 2 * t;
            float2 wa = __half22float2(*(const __half2*)&smWS[r0 * 72 + col]);
            float2 wb = __half22float2(*(const __half2*)&smWS[(r0 + 8) * 72 + col]);
            cs[nt][0] *= SCALE * wa.x; cs[nt][1] *= SCALE * wa.y;
            cs[nt][2] *= SCALE * wb.x; cs[nt][3] *= SCALE * wb.y;
            mloc0 = fmaxf(mloc0, fmaxf(cs[nt][0], cs[nt][1]));
            mloc1 = fmaxf(mloc1, fmaxf(cs[nt][2], cs[nt][3]));
        }
        #pragma unroll
        for (int o = 1; o <= 2; o <<= 1) {
            mloc0 = fmaxf(mloc0, __shfl_xor_sync(0xffffffffu, mloc0, o));
            mloc1 = fmaxf(mloc1, __shfl_xor_sync(0xffffffffu, mloc1, o));
        }
        float mn0 = fmaxf(mA, mloc0), mn1 = fmaxf(mB, mloc1);
        float corr0 = __expf(mA - mn0), corr1 = __expf(mB - mn1);
        mA = mn0; mB = mn1;
        float rs0 = 0.f, rs1 = 0.f;
        uint32_t plo[8], phi[8];
        #pragma unroll
        for (int nt = 0; nt < 8; nt++) {
            float p0 = __expf(cs[nt][0] - mn0), p1 = __expf(cs[nt][1] - mn0);
            float p2 = __expf(cs[nt][2] - mn1), p3 = __expf(cs[nt][3] - mn1);
            rs0 += p0 + p1; rs1 += p2 + p3;
            __half2 a = __floats2half2_rn(p0, p1);
            __half2 bb = __floats2half2_rn(p2, p3);
            plo[nt] = *(uint32_t*)&a;
            phi[nt] = *(uint32_t*)&bb;
        }
        #pragma unroll
        for (int o = 1; o <= 2; o <<= 1) {
            rs0 += __shfl_xor_sync(0xffffffffu, rs0, o);
            rs1 += __shfl_xor_sync(0xffffffffu, rs1, o);
        }
        lA = lA * corr0 + rs0;
        lB = lB * corr1 + rs1;
        #pragma unroll
        for (int nt = 0; nt < 8; nt++) {
            co[nt][0] *= corr0; co[nt][1] *= corr0;
            co[nt][2] *= corr1; co[nt][3] *= corr1;
        }

        // ---- PV: plain fp16 from registers ----
        #pragma unroll
        for (int ks = 0; ks < 4; ks++) {
            uint32_t pa[4] = {plo[2 * ks], phi[2 * ks], plo[2 * ks + 1], phi[2 * ks + 1]};
            #pragma unroll
            for (int nt = 0; nt < 8; nt++) {
                int base = (hb + 8 * nt + g) * 136 + 16 * ks + 2 * t;
                uint32_t b0 = *(const uint32_t*)&smV[base];
                uint32_t b1 = *(const uint32_t*)&smV[base + 8];
                mma16(co[nt], pa, b0, b1);
            }
        }
        __syncthreads();   // prefetch stores drained; all reads of buf p done
    }

    // ---- epilogue: unnormalized partials + (m, l) ----
    float* po = g_po[split];
    int row0 = b * SEQ + i0 + rbase + g;
    #pragma unroll
    for (int nt = 0; nt < 8; nt++) {
        int col = hb + 8 * nt + 2 * t;
        float2 o0 = {co[nt][0], co[nt][1]};
        float2 o1 = {co[nt][2], co[nt][3]};
        *(float2*)&po[(size_t)row0 * 128 + col] = o0;
        *(float2*)&po[(size_t)(row0 + 8) * 128 + col] = o1;
    }
    if (t == 0) {
        g_pml[split][row0 * 2 + h]       = make_float2(mA, lA);
        g_pml[split][(row0 + 8) * 2 + h] = make_float2(mB, lB);
    }
}

// ---------------- merge split-KV partials ----------------
__global__ void k_merge() {
    int idx = blockIdx.x * 256 + threadIdx.x;
    int row = idx >> 7, col = idx & 127;
    int h = col >> 6;
    float2 a = g_pml[0][row * 2 + h];
    float2 bb = g_pml[1][row * 2 + h];
    float M = fmaxf(a.x, bb.x);
    float ea = __expf(a.x - M), eb = __expf(bb.x - M);
    float l = ea * a.y + eb * bb.y;
    float o = (ea * g_po[0][idx] + eb * g_po[1][idx]) / l;
    g_attn[idx] = o;
}

// ---------------- launch ----------------
extern "C" void kernel_launch(void* const* d_in, const int* in_sizes, int n_in,
                              void* d_out, int out_size) {
    const float* x      = (const float*)d_in[0];
    const float* v_qkv  = (const float*)d_in[1];
    const float* g_qkv_ = (const float*)d_in[2];
    const float* b_qkv  = (const float*)d_in[3];
    const float* v_ff1  = (const float*)d_in[4];
    const float* g_ff1  = (const float*)d_in[5];
    const float* b_ff1  = (const float*)d_in[6];
    const float* v_ff2  = (const float*)d_in[7];
    const float* g_ff2  = (const float*)d_in[8];
    const float* b_ff2  = (const float*)d_in[9];
    float* out = (float*)d_out;

    cudaFuncSetAttribute(k_gemm128, cudaFuncAttributeMaxDynamicSharedMemorySize, PG_SMEM_BYTES);
    cudaFuncSetAttribute(k_dist,    cudaFuncAttributeMaxDynamicSharedMemorySize, DIST_SMEM_BYTES);
    cudaFuncSetAttribute(k_flash,   cudaFuncAttributeMaxDynamicSharedMemorySize, FLASH_SMEM_BYTES);

    float* Wdev = nullptr;     cudaGetSymbolAddress((void**)&Wdev, g_W);
    float* attn_dev = nullptr; cudaGetSymbolAddress((void**)&attn_dev, g_attn);
    float* h1_dev = nullptr;   cudaGetSymbolAddress((void**)&h1_dev, g_q);

    // launch order: k_flash is 4th (ncu capture slot)
    k_weights_sq<<<640 + NTOK / 4, 128>>>(v_qkv, g_qkv_, v_ff1, g_ff1, v_ff2, g_ff2, x);
    k_gemm128<<<dim3(3, NTOK / 128), 256, PG_SMEM_BYTES>>>(x, Wdev, b_qkv, nullptr, 0);
    k_dist<<<dim3(32, 32, BATCH), 256, DIST_SMEM_BYTES>>>();
    k_flash<<<dim3(SEQ / 128, NSPLIT, BATCH), 512, FLASH_SMEM_BYTES>>>();
    k_merge<<<NTOK * DIM / 256, 256>>>();
    k_gemm128<<<dim3(1, NTOK / 128), 256, PG_SMEM_BYTES>>>(attn_dev, Wdev + 384 * 128, b_ff1, nullptr, 1);
    k_gemm128<<<dim3(1, NTOK / 128), 256, PG_SMEM_BYTES>>>(h1_dev, Wdev + 512 * 128, b_ff2, out, 2);
}